// round 4
// baseline (speedup 1.0000x reference)
#include <cuda_runtime.h>
#include <cstdint>

// Problem constants
#define BATCH 16
#define CDIM  768          // channels = HEADS * DHEAD
#define NTOK  4096         // H*W
#define HEADS 12
#define DHEAD 64

// Scratch (no cudaMalloc allowed -> __device__ globals)
__device__ float g_wbuf[(size_t)BATCH * CDIM * NTOK];   // w[b][co][n]  (~201 MB)
__device__ float g_Pi[(size_t)BATCH * HEADS * NTOK];    // Pi[b][h][n]
__device__ float g_inv2[BATCH * CDIM];                  // 1/max(||w_row||,1e-12)^2
__device__ float g_attn[BATCH * CDIM];                  // 1/(1+dots)
__device__ float g_PiSum[BATCH * HEADS];

// ---------------------------------------------------------------------------
// block reduce (deterministic fixed-order)
// ---------------------------------------------------------------------------
__device__ __forceinline__ float blockReduceSum(float v) {
    __shared__ float sh[32];
    int lane = threadIdx.x & 31, wid = threadIdx.x >> 5;
    #pragma unroll
    for (int o = 16; o; o >>= 1) v += __shfl_down_sync(0xffffffffu, v, o);
    if (lane == 0) sh[wid] = v;
    __syncthreads();
    int nw = blockDim.x >> 5;
    v = (threadIdx.x < nw) ? sh[threadIdx.x] : 0.f;
    if (wid == 0) {
        #pragma unroll
        for (int o = 16; o; o >>= 1) v += __shfl_down_sync(0xffffffffu, v, o);
    }
    return v;  // valid in thread 0
}

// ---------------------------------------------------------------------------
// SGEMM: C[z][m][n] = sum_k A[m][k] * B[z][k][n]
//   M=768, N=4096, K=768. 128x128 tile, BK=8, 8x8 per thread, 256 threads,
//   double-buffered smem, split-fragment layout (conflict-free LDS).
//   SCALED=false: B = Bext (x), C = g_wbuf
//   SCALED=true : B = -g_wbuf * Pi[b,h,n] * attn[b,co], C = Cext (d_out)
// ---------------------------------------------------------------------------
template <bool SCALED>
__global__ __launch_bounds__(256)
void sgemm_kernel(const float* __restrict__ A,
                  const float* __restrict__ Bext,
                  float* __restrict__ Cext)
{
    constexpr int Mv = CDIM, Nv = NTOK, Kv = CDIM, BK = 8;
    constexpr int T = Kv / BK;  // 96

    __shared__ float As[2][BK][128];
    __shared__ float Bs[2][BK][128];

    const int z    = blockIdx.z;
    const int mBlk = blockIdx.y;
    const int nBlk = blockIdx.x;

    const float* Bb = SCALED ? (g_wbuf + (size_t)z * Kv * Nv)
                             : (Bext   + (size_t)z * Kv * Nv);
    float* Cb = SCALED ? (Cext + (size_t)z * Mv * Nv)
                       : (g_wbuf + (size_t)z * Mv * Nv);

    const int tid  = threadIdx.x;
    const int arow = tid >> 1;          // 0..127
    const int acol = (tid & 1) * 4;     // 0 or 4
    const int brow = tid >> 5;          // 0..7
    const int bcol = (tid & 31) * 4;    // 0..124
    const int trow = (tid >> 4) * 4;    // 0..60
    const int tcol = (tid & 15) * 4;    // 0..60

    const float* Ap = A  + (size_t)(mBlk * 128 + arow) * Kv + acol;
    const float* Bp = Bb + (size_t)brow * Nv + nBlk * 128 + bcol;

    auto loadB = [&](int t) -> float4 {
        float4 v = *(const float4*)(Bp + (size_t)t * BK * Nv);
        if (SCALED) {
            int co = t * BK + brow;
            const float4 pv = *(const float4*)(g_Pi
                + (size_t)(z * HEADS + (co >> 6)) * NTOK + nBlk * 128 + bcol);
            float a = g_attn[z * CDIM + co];
            v.x = -v.x * pv.x * a;
            v.y = -v.y * pv.y * a;
            v.z = -v.z * pv.z * a;
            v.w = -v.w * pv.w * a;
        }
        return v;
    };

    // prologue: tile 0
    float4 av = *(const float4*)Ap;
    float4 bv = loadB(0);
    As[0][acol + 0][arow] = av.x;
    As[0][acol + 1][arow] = av.y;
    As[0][acol + 2][arow] = av.z;
    As[0][acol + 3][arow] = av.w;
    *(float4*)&Bs[0][brow][bcol] = bv;
    __syncthreads();

    float acc[8][8];
    #pragma unroll
    for (int i = 0; i < 8; i++)
        #pragma unroll
        for (int j = 0; j < 8; j++) acc[i][j] = 0.f;

    #pragma unroll 1
    for (int t = 0; t < T; t++) {
        const int cur = t & 1, nxt = cur ^ 1;
        if (t + 1 < T) {
            av = *(const float4*)(Ap + (size_t)(t + 1) * BK);
            bv = loadB(t + 1);
        }
        #pragma unroll
        for (int k = 0; k < BK; k++) {
            float ra[8], rb[8];
            *(float4*)&ra[0] = *(const float4*)&As[cur][k][trow];
            *(float4*)&ra[4] = *(const float4*)&As[cur][k][trow + 64];
            *(float4*)&rb[0] = *(const float4*)&Bs[cur][k][tcol];
            *(float4*)&rb[4] = *(const float4*)&Bs[cur][k][tcol + 64];
            #pragma unroll
            for (int i = 0; i < 8; i++)
                #pragma unroll
                for (int j = 0; j < 8; j++)
                    acc[i][j] = fmaf(ra[i], rb[j], acc[i][j]);
        }
        if (t + 1 < T) {
            As[nxt][acol + 0][arow] = av.x;
            As[nxt][acol + 1][arow] = av.y;
            As[nxt][acol + 2][arow] = av.z;
            As[nxt][acol + 3][arow] = av.w;
            *(float4*)&Bs[nxt][brow][bcol] = bv;
        }
        __syncthreads();
    }

    // epilogue
    #pragma unroll
    for (int ih = 0; ih < 2; ih++) {
        #pragma unroll
        for (int i = 0; i < 4; i++) {
            int m = mBlk * 128 + ih * 64 + trow + i;
            float* cp = Cb + (size_t)m * Nv + nBlk * 128 + tcol;
            float4 c0 = make_float4(acc[ih * 4 + i][0], acc[ih * 4 + i][1],
                                    acc[ih * 4 + i][2], acc[ih * 4 + i][3]);
            float4 c1 = make_float4(acc[ih * 4 + i][4], acc[ih * 4 + i][5],
                                    acc[ih * 4 + i][6], acc[ih * 4 + i][7]);
            *(float4*)cp       = c0;
            *(float4*)(cp + 64) = c1;
        }
    }
}

// ---------------------------------------------------------------------------
// per-row (b,co) sum of squares over n -> inv2 = 1/max(sqrt(s),1e-12)^2
// grid = BATCH*CDIM blocks x 256 threads
// ---------------------------------------------------------------------------
__global__ void rownorm_kernel() {
    size_t row = blockIdx.x;
    const float4* p = (const float4*)(g_wbuf + row * NTOK);
    float s = 0.f;
    for (int i = threadIdx.x; i < NTOK / 4; i += 256) {
        float4 v = p[i];
        s += v.x * v.x + v.y * v.y + v.z * v.z + v.w * v.w;
    }
    s = blockReduceSum(s);
    if (threadIdx.x == 0) {
        float nrm = fmaxf(sqrtf(s), 1e-12f);
        g_inv2[row] = 1.f / (nrm * nrm);
    }
}

// ---------------------------------------------------------------------------
// per-(b,n): logits over heads (sum_d w^2 * inv2 * temp), softmax over heads
// grid = (NTOK/128, BATCH), 128 threads; thread <-> one n
// ---------------------------------------------------------------------------
__global__ void softheads_kernel(const float* __restrict__ temp) {
    const int b = blockIdx.y;
    const int n = blockIdx.x * 128 + threadIdx.x;
    __shared__ float s_inv2[CDIM];
    for (int i = threadIdx.x; i < CDIM; i += 128) s_inv2[i] = g_inv2[b * CDIM + i];
    __syncthreads();

    const float* base = g_wbuf + (size_t)b * CDIM * NTOK + n;
    float logit[HEADS];
    #pragma unroll
    for (int h = 0; h < HEADS; h++) {
        float a = 0.f;
        #pragma unroll 8
        for (int d = 0; d < DHEAD; d++) {
            float v = base[(size_t)(h * DHEAD + d) * NTOK];
            a = fmaf(v * v, s_inv2[h * DHEAD + d], a);
        }
        logit[h] = a * temp[h];
    }
    float m = logit[0];
    #pragma unroll
    for (int h = 1; h < HEADS; h++) m = fmaxf(m, logit[h]);
    float s = 0.f, e[HEADS];
    #pragma unroll
    for (int h = 0; h < HEADS; h++) { e[h] = expf(logit[h] - m); s += e[h]; }
    float inv = 1.f / s;
    float* pp = g_Pi + (size_t)b * HEADS * NTOK + n;
    #pragma unroll
    for (int h = 0; h < HEADS; h++) pp[(size_t)h * NTOK] = e[h] * inv;
}

// ---------------------------------------------------------------------------
// Pi_sum[b,h] = sum_n Pi ; grid = BATCH*HEADS x 256
// ---------------------------------------------------------------------------
__global__ void pisum_kernel() {
    int row = blockIdx.x;  // b*HEADS+h
    const float* p = g_Pi + (size_t)row * NTOK;
    float s = 0.f;
    for (int i = threadIdx.x; i < NTOK; i += 256) s += p[i];
    s = blockReduceSum(s);
    if (threadIdx.x == 0) g_PiSum[row] = s;
}

// ---------------------------------------------------------------------------
// dots[b,co] = (sum_n Pi[b,h,n]*w^2) / (PiSum+1e-8); attn = 1/(1+dots)
// grid = BATCH*CDIM x 256
// ---------------------------------------------------------------------------
__global__ void dots_kernel() {
    int row = blockIdx.x;          // b*CDIM + co
    int b = row / CDIM;
    int co = row - b * CDIM;
    int h = co >> 6;
    const float* wp = g_wbuf + (size_t)row * NTOK;
    const float* pp = g_Pi + (size_t)(b * HEADS + h) * NTOK;
    float s = 0.f;
    for (int i = threadIdx.x; i < NTOK; i += 256) {
        float v = wp[i];
        s = fmaf(v * v, pp[i], s);
    }
    s = blockReduceSum(s);
    if (threadIdx.x == 0) {
        float dots = s / (g_PiSum[b * HEADS + h] + 1e-8f);
        g_attn[row] = 1.f / (1.f + dots);
    }
}

// ---------------------------------------------------------------------------
// launch
// ---------------------------------------------------------------------------
extern "C" void kernel_launch(void* const* d_in, const int* in_sizes, int n_in,
                              void* d_out, int out_size) {
    (void)in_sizes; (void)n_in; (void)out_size;
    const float* x      = (const float*)d_in[0];  // [B, C, H, W]
    const float* W_qkv  = (const float*)d_in[1];  // [C, C]
    const float* W_out  = (const float*)d_in[2];  // [C, C]
    const float* temp   = (const float*)d_in[3];  // [HEADS, 1]
    float* out = (float*)d_out;                   // [B, C, H, W]

    dim3 gemmGrid(NTOK / 128, CDIM / 128, BATCH);  // (32, 6, 16)

    // 1) w = W_qkv @ x  (per batch)
    sgemm_kernel<false><<<gemmGrid, 256>>>(W_qkv, x, nullptr);
    // 2) per-row inv norm^2
    rownorm_kernel<<<BATCH * CDIM, 256>>>();
    // 3) head-softmax Pi
    softheads_kernel<<<dim3(NTOK / 128, BATCH), 128>>>(temp);
    // 4) Pi row sums
    pisum_kernel<<<BATCH * HEADS, 256>>>();
    // 5) dots -> attn
    dots_kernel<<<BATCH * CDIM, 256>>>();
    // 6) out = W_out @ (-w * Pi * attn)  (per batch), direct [B,C,H,W] layout
    sgemm_kernel<true><<<gemmGrid, 256>>>(W_out, nullptr, out);
}

// round 9
// speedup vs baseline: 1.8198x; 1.8198x over previous
#include <cuda_runtime.h>
#include <cuda_bf16.h>
#include <cstdint>

// Problem constants
#define BATCH 16
#define CDIM  768
#define NTOK  4096
#define HEADS 12
#define DHEAD 64

// ---------------------------------------------------------------------------
// Scratch (__device__ globals; no cudaMalloc allowed)
// ---------------------------------------------------------------------------
__device__ float g_wbuf[(size_t)BATCH * CDIM * NTOK];       // w[b][co][n] fp32
__device__ float g_Pi[(size_t)BATCH * HEADS * NTOK];
__device__ float g_inv2[BATCH * CDIM];
__device__ float g_attn[BATCH * CDIM];
__device__ float g_PiSum[BATCH * HEADS];
__device__ __nv_bfloat16 g_Ah[2 * CDIM * CDIM];             // [W_qkv ; W_out] hi, [m][k]
__device__ __nv_bfloat16 g_Al[2 * CDIM * CDIM];             // lo
__device__ __nv_bfloat16 g_Bh[(size_t)BATCH * NTOK * CDIM]; // B hi, [b][n][k]
__device__ __nv_bfloat16 g_Bl[(size_t)BATCH * NTOK * CDIM]; // B lo

// ---------------------------------------------------------------------------
// PTX helpers (baseline sm_80+ features only: cp.async, ldmatrix, mma.sync)
// ---------------------------------------------------------------------------
__device__ __forceinline__ uint32_t smem_to_u32(const void* p) {
    uint32_t a;
    asm("{ .reg .u64 t; cvta.to.shared.u64 t, %1; cvt.u32.u64 %0, t; }" : "=r"(a) : "l"(p));
    return a;
}
#define CP_ASYNC16(dst, src) asm volatile( \
    "cp.async.cg.shared.global [%0], [%1], 16;" :: "r"(dst), "l"(src) : "memory")
#define CP_COMMIT() asm volatile("cp.async.commit_group;" ::: "memory")
template <int N>
__device__ __forceinline__ void cp_wait_group() {
    asm volatile("cp.async.wait_group %0;" :: "n"(N) : "memory");
}
#define LDSM4(r0, r1, r2, r3, addr) asm volatile( \
    "ldmatrix.sync.aligned.m8n8.x4.shared.b16 {%0,%1,%2,%3}, [%4];" \
    : "=r"(r0), "=r"(r1), "=r"(r2), "=r"(r3) : "r"(addr))

__device__ __forceinline__ void mma16816(float* c, const uint32_t* a, const uint32_t* b) {
    asm volatile(
        "mma.sync.aligned.m16n8k16.row.col.f32.bf16.bf16.f32 "
        "{%0,%1,%2,%3}, {%4,%5,%6,%7}, {%8,%9}, {%0,%1,%2,%3};"
        : "+f"(c[0]), "+f"(c[1]), "+f"(c[2]), "+f"(c[3])
        : "r"(a[0]), "r"(a[1]), "r"(a[2]), "r"(a[3]), "r"(b[0]), "r"(b[1]));
}

// ---------------------------------------------------------------------------
// GEMM: C[z][m][n] = sum_k A[m][k] * B[z][n][k]   (bf16 hi/lo 3-term split)
// M=768, N=4096, K=768. CTA tile 128x128, BK=32, 3-stage cp.async pipeline.
// 256 threads = 8 warps (2 x 4); each warp computes 64x32.
// smem per array: 128 rows x 80B (32 bf16 data + pad), conflict-free ldmatrix.
// ---------------------------------------------------------------------------
#define TILE 128
#define BK 32
#define T_TILES 24                 // 768 / 32
#define ROWB 80                    // padded row bytes (32*2 data + 16 pad)
#define ABYTES (TILE * ROWB)       // 10240 per array
#define STAGE_BYTES (4 * ABYTES)   // Ah, Al, Bh, Bl
#define STAGES 3
#define SMEM_GEMM (STAGES * STAGE_BYTES)   // 122880

template <int PASS>  // 0: w = Wqkv@x -> g_wbuf ; 1: out = Wout@V -> outp
__global__ void __launch_bounds__(256, 1)
gemm_mma_kernel(float* __restrict__ outp)
{
    extern __shared__ char smem[];
    const uint32_t su = smem_to_u32(smem);
    const int tid = threadIdx.x;
    const int wid = tid >> 5, lid = tid & 31;
    const int nBlk = blockIdx.x, mBlk = blockIdx.y, z = blockIdx.z;

    const __nv_bfloat16* bases[4];
    bases[0] = g_Ah + (size_t)PASS * CDIM * CDIM + (size_t)mBlk * TILE * CDIM;
    bases[1] = g_Al + (size_t)PASS * CDIM * CDIM + (size_t)mBlk * TILE * CDIM;
    bases[2] = g_Bh + ((size_t)z * NTOK + (size_t)nBlk * TILE) * CDIM;
    bases[3] = g_Bl + ((size_t)z * NTOK + (size_t)nBlk * TILE) * CDIM;

    auto prefetch = [&](int t, int s) {
        const uint32_t sb = su + s * STAGE_BYTES;
        const int koff = t * BK;
        #pragma unroll
        for (int q = 0; q < 8; q++) {
            const int i   = q * 256 + tid;     // 0..2047
            const int arr = i >> 9;
            const int idx = i & 511;
            const int row = idx >> 2, col = idx & 3;
            const __nv_bfloat16* src = bases[arr] + (size_t)row * CDIM + koff + col * 8;
            const uint32_t dst = sb + arr * ABYTES + row * ROWB + col * 16;
            CP_ASYNC16(dst, src);
        }
        CP_COMMIT();
    };

    prefetch(0, 0); prefetch(1, 1); prefetch(2, 2);

    // warp tiling: 2 (m) x 4 (n)
    const int mbase = (wid >> 2) * 64;
    const int nbase = (wid & 3) * 32;
    const int li = lid >> 3, lj = lid & 7;
    // ldmatrix per-lane offsets (bytes) within an array
    const uint32_t aoff = (uint32_t)(mbase + (li & 1) * 8 + lj) * ROWB + (li >> 1) * 16;
    const uint32_t boff = (uint32_t)(nbase + (li >> 1) * 8 + lj) * ROWB + (li & 1) * 16;

    float acc[4][4][4];
    #pragma unroll
    for (int mi = 0; mi < 4; mi++)
        #pragma unroll
        for (int ni = 0; ni < 4; ni++)
            #pragma unroll
            for (int r = 0; r < 4; r++) acc[mi][ni][r] = 0.f;

    for (int t = 0; t < T_TILES; t++) {
        const int s = t % STAGES;
        cp_wait_group<STAGES - 1>();
        __syncthreads();

        const uint32_t sAh = su + s * STAGE_BYTES;
        const uint32_t sAl = sAh + ABYTES;
        const uint32_t sBh = sAh + 2 * ABYTES;
        const uint32_t sBl = sAh + 3 * ABYTES;

        #pragma unroll
        for (int ks = 0; ks < 2; ks++) {
            const uint32_t ko = ks * 32;   // k-offset bytes (16 bf16)
            uint32_t ah[4][4], al[4][4], bh[4][2], bl[4][2];
            #pragma unroll
            for (int mi = 0; mi < 4; mi++) {
                LDSM4(ah[mi][0], ah[mi][1], ah[mi][2], ah[mi][3],
                      sAh + aoff + mi * (16 * ROWB) + ko);
                LDSM4(al[mi][0], al[mi][1], al[mi][2], al[mi][3],
                      sAl + aoff + mi * (16 * ROWB) + ko);
            }
            #pragma unroll
            for (int bi = 0; bi < 2; bi++) {
                uint32_t r0, r1, r2, r3;
                LDSM4(r0, r1, r2, r3, sBh + boff + bi * (16 * ROWB) + ko);
                bh[bi * 2][0] = r0; bh[bi * 2][1] = r1;
                bh[bi * 2 + 1][0] = r2; bh[bi * 2 + 1][1] = r3;
                LDSM4(r0, r1, r2, r3, sBl + boff + bi * (16 * ROWB) + ko);
                bl[bi * 2][0] = r0; bl[bi * 2][1] = r1;
                bl[bi * 2 + 1][0] = r2; bl[bi * 2 + 1][1] = r3;
            }
            #pragma unroll
            for (int mi = 0; mi < 4; mi++)
                #pragma unroll
                for (int ni = 0; ni < 4; ni++) {
                    mma16816(acc[mi][ni], ah[mi], bh[ni]);
                    mma16816(acc[mi][ni], al[mi], bh[ni]);
                    mma16816(acc[mi][ni], ah[mi], bl[ni]);
                }
        }
        __syncthreads();
        if (t + STAGES < T_TILES) prefetch(t + STAGES, s);
        else CP_COMMIT();   // empty group keeps wait_group accounting aligned
    }

    // epilogue: write fp32 C
    float* Cb = (PASS ? outp : g_wbuf) + (size_t)z * CDIM * NTOK;
    const int gr0 = mBlk * TILE + mbase + (lid >> 2);
    const int gc0 = nBlk * TILE + nbase + (lid & 3) * 2;
    #pragma unroll
    for (int mi = 0; mi < 4; mi++)
        #pragma unroll
        for (int ni = 0; ni < 4; ni++) {
            float* p = Cb + (size_t)(gr0 + mi * 16) * NTOK + gc0 + ni * 8;
            *(float2*)p = make_float2(acc[mi][ni][0], acc[mi][ni][1]);
            *(float2*)(p + (size_t)8 * NTOK) = make_float2(acc[mi][ni][2], acc[mi][ni][3]);
        }
}

// ---------------------------------------------------------------------------
// Split W_qkv / W_out into bf16 hi+lo (K-major layout preserved)
// ---------------------------------------------------------------------------
__global__ void splitW_kernel(const float* __restrict__ Wq, const float* __restrict__ Wo) {
    int i = blockIdx.x * 256 + threadIdx.x;
    if (i >= 2 * CDIM * CDIM) return;
    float v = (i < CDIM * CDIM) ? Wq[i] : Wo[i - CDIM * CDIM];
    __nv_bfloat16 h = __float2bfloat16(v);
    __nv_bfloat16 l = __float2bfloat16(v - __bfloat162float(h));
    g_Ah[i] = h; g_Al[i] = l;
}

// ---------------------------------------------------------------------------
// Transpose [b][c][n] fp32 -> [b][n][c] bf16 hi/lo.  SCALED applies
// v = -w * Pi[b,h(c),n] * attn[b,c] (GEMM2 operand); else v = x.
// ---------------------------------------------------------------------------
template <bool SCALED>
__global__ void split_transpose_kernel(const float* __restrict__ in) {
    __shared__ float tile[32][33];
    const int b = blockIdx.z;
    const int n0 = blockIdx.x * 32, c0 = blockIdx.y * 32;
    const int tx = threadIdx.x, ty = threadIdx.y;
    const float* src = (SCALED ? g_wbuf : in) + (size_t)b * CDIM * NTOK;
    #pragma unroll
    for (int r = 0; r < 4; r++) {
        int c = c0 + ty + r * 8;
        float v = src[(size_t)c * NTOK + n0 + tx];
        if (SCALED) {
            int h = c >> 6;
            v = -v * g_Pi[((size_t)b * HEADS + h) * NTOK + n0 + tx] * g_attn[b * CDIM + c];
        }
        tile[ty + r * 8][tx] = v;
    }
    __syncthreads();
    const size_t obase = ((size_t)b * NTOK + n0) * CDIM + c0;
    #pragma unroll
    for (int r = 0; r < 4; r++) {
        int nn = ty + r * 8;
        float v = tile[tx][nn];
        __nv_bfloat16 h = __float2bfloat16(v);
        __nv_bfloat16 l = __float2bfloat16(v - __bfloat162float(h));
        g_Bh[obase + (size_t)nn * CDIM + tx] = h;
        g_Bl[obase + (size_t)nn * CDIM + tx] = l;
    }
}

// ---------------------------------------------------------------------------
// Stats kernels (unchanged from passing R4 version)
// ---------------------------------------------------------------------------
__device__ __forceinline__ float blockReduceSum(float v) {
    __shared__ float sh[32];
    int lane = threadIdx.x & 31, wid = threadIdx.x >> 5;
    #pragma unroll
    for (int o = 16; o; o >>= 1) v += __shfl_down_sync(0xffffffffu, v, o);
    if (lane == 0) sh[wid] = v;
    __syncthreads();
    int nw = blockDim.x >> 5;
    v = (threadIdx.x < nw) ? sh[threadIdx.x] : 0.f;
    if (wid == 0) {
        #pragma unroll
        for (int o = 16; o; o >>= 1) v += __shfl_down_sync(0xffffffffu, v, o);
    }
    return v;
}

__global__ void rownorm_kernel() {
    size_t row = blockIdx.x;
    const float4* p = (const float4*)(g_wbuf + row * NTOK);
    float s = 0.f;
    for (int i = threadIdx.x; i < NTOK / 4; i += 256) {
        float4 v = p[i];
        s += v.x * v.x + v.y * v.y + v.z * v.z + v.w * v.w;
    }
    s = blockReduceSum(s);
    if (threadIdx.x == 0) {
        float nrm = fmaxf(sqrtf(s), 1e-12f);
        g_inv2[row] = 1.f / (nrm * nrm);
    }
}

__global__ void softheads_kernel(const float* __restrict__ temp) {
    const int b = blockIdx.y;
    const int n = blockIdx.x * 128 + threadIdx.x;
    __shared__ float s_inv2[CDIM];
    for (int i = threadIdx.x; i < CDIM; i += 128) s_inv2[i] = g_inv2[b * CDIM + i];
    __syncthreads();
    const float* base = g_wbuf + (size_t)b * CDIM * NTOK + n;
    float logit[HEADS];
    #pragma unroll
    for (int h = 0; h < HEADS; h++) {
        float a = 0.f;
        #pragma unroll 8
        for (int d = 0; d < DHEAD; d++) {
            float v = base[(size_t)(h * DHEAD + d) * NTOK];
            a = fmaf(v * v, s_inv2[h * DHEAD + d], a);
        }
        logit[h] = a * temp[h];
    }
    float m = logit[0];
    #pragma unroll
    for (int h = 1; h < HEADS; h++) m = fmaxf(m, logit[h]);
    float s = 0.f, e[HEADS];
    #pragma unroll
    for (int h = 0; h < HEADS; h++) { e[h] = expf(logit[h] - m); s += e[h]; }
    float inv = 1.f / s;
    float* pp = g_Pi + (size_t)b * HEADS * NTOK + n;
    #pragma unroll
    for (int h = 0; h < HEADS; h++) pp[(size_t)h * NTOK] = e[h] * inv;
}

__global__ void pisum_kernel() {
    int row = blockIdx.x;
    const float* p = g_Pi + (size_t)row * NTOK;
    float s = 0.f;
    for (int i = threadIdx.x; i < NTOK; i += 256) s += p[i];
    s = blockReduceSum(s);
    if (threadIdx.x == 0) g_PiSum[row] = s;
}

__global__ void dots_kernel() {
    int row = blockIdx.x;
    int b = row / CDIM;
    int co = row - b * CDIM;
    int h = co >> 6;
    const float* wp = g_wbuf + (size_t)row * NTOK;
    const float* pp = g_Pi + (size_t)(b * HEADS + h) * NTOK;
    float s = 0.f;
    for (int i = threadIdx.x; i < NTOK; i += 256) {
        float v = wp[i];
        s = fmaf(v * v, pp[i], s);
    }
    s = blockReduceSum(s);
    if (threadIdx.x == 0) {
        float dots = s / (g_PiSum[b * HEADS + h] + 1e-8f);
        g_attn[row] = 1.f / (1.f + dots);
    }
}

// ---------------------------------------------------------------------------
// launch
// ---------------------------------------------------------------------------
extern "C" void kernel_launch(void* const* d_in, const int* in_sizes, int n_in,
                              void* d_out, int out_size) {
    (void)in_sizes; (void)n_in; (void)out_size;
    const float* x     = (const float*)d_in[0];
    const float* W_qkv = (const float*)d_in[1];
    const float* W_out = (const float*)d_in[2];
    const float* temp  = (const float*)d_in[3];
    float* out = (float*)d_out;

    static bool attr_set = false;
    cudaFuncSetAttribute(gemm_mma_kernel<0>, cudaFuncAttributeMaxDynamicSharedMemorySize, SMEM_GEMM);
    cudaFuncSetAttribute(gemm_mma_kernel<1>, cudaFuncAttributeMaxDynamicSharedMemorySize, SMEM_GEMM);
    (void)attr_set;

    dim3 gemmGrid(NTOK / TILE, CDIM / TILE, BATCH);     // (32, 6, 16)
    dim3 trGrid(NTOK / 32, CDIM / 32, BATCH);
    dim3 trBlk(32, 8);

    splitW_kernel<<<(2 * CDIM * CDIM + 255) / 256, 256>>>(W_qkv, W_out);
    split_transpose_kernel<false><<<trGrid, trBlk>>>(x);
    gemm_mma_kernel<0><<<gemmGrid, 256, SMEM_GEMM>>>(nullptr);
    rownorm_kernel<<<BATCH * CDIM, 256>>>();
    softheads_kernel<<<dim3(NTOK / 128, BATCH), 128>>>(temp);
    pisum_kernel<<<BATCH * HEADS, 256>>>();
    dots_kernel<<<BATCH * CDIM, 256>>>();
    split_transpose_kernel<true><<<trGrid, trBlk>>>(nullptr);
    gemm_mma_kernel<1><<<gemmGrid, 256, SMEM_GEMM>>>(out);
}

// round 10
// speedup vs baseline: 2.3910x; 1.3139x over previous
#include <cuda_runtime.h>
#include <cuda_fp16.h>
#include <cstdint>

// Problem constants
#define BATCH 16
#define CDIM  768
#define NTOK  4096
#define HEADS 12
#define DHEAD 64

// ---------------------------------------------------------------------------
// Scratch (__device__ globals; no cudaMalloc allowed)
// ---------------------------------------------------------------------------
__device__ float g_wbuf[(size_t)BATCH * CDIM * NTOK];       // w[b][co][n] fp32
__device__ float g_Pi[(size_t)BATCH * HEADS * NTOK];
__device__ float g_inv2[BATCH * CDIM];
__device__ float g_attn[BATCH * CDIM];
__device__ float g_PiSum[BATCH * HEADS];
__device__ __half g_Ah[2 * CDIM * CDIM];                    // [W_qkv ; W_out] hi, [m][k]
__device__ __half g_Al[2 * CDIM * CDIM];                    // lo (fp16 residual)
__device__ __half g_Bh[(size_t)BATCH * NTOK * CDIM];        // B operand fp16, [b][n][k]

// ---------------------------------------------------------------------------
// PTX helpers (baseline sm_80+ features only: cp.async, ldmatrix, mma.sync)
// ---------------------------------------------------------------------------
__device__ __forceinline__ uint32_t smem_to_u32(const void* p) {
    uint32_t a;
    asm("{ .reg .u64 t; cvta.to.shared.u64 t, %1; cvt.u32.u64 %0, t; }" : "=r"(a) : "l"(p));
    return a;
}
#define CP_ASYNC16(dst, src) asm volatile( \
    "cp.async.cg.shared.global [%0], [%1], 16;" :: "r"(dst), "l"(src) : "memory")
#define CP_COMMIT() asm volatile("cp.async.commit_group;" ::: "memory")
template <int N>
__device__ __forceinline__ void cp_wait_group() {
    asm volatile("cp.async.wait_group %0;" :: "n"(N) : "memory");
}
#define LDSM4(r0, r1, r2, r3, addr) asm volatile( \
    "ldmatrix.sync.aligned.m8n8.x4.shared.b16 {%0,%1,%2,%3}, [%4];" \
    : "=r"(r0), "=r"(r1), "=r"(r2), "=r"(r3) : "r"(addr))

__device__ __forceinline__ void mma16816h(float* c, const uint32_t* a, const uint32_t* b) {
    asm volatile(
        "mma.sync.aligned.m16n8k16.row.col.f32.f16.f16.f32 "
        "{%0,%1,%2,%3}, {%4,%5,%6,%7}, {%8,%9}, {%0,%1,%2,%3};"
        : "+f"(c[0]), "+f"(c[1]), "+f"(c[2]), "+f"(c[3])
        : "r"(a[0]), "r"(a[1]), "r"(a[2]), "r"(a[3]), "r"(b[0]), "r"(b[1]));
}

// ---------------------------------------------------------------------------
// GEMM: C[z][m][n] = sum_k A[m][k] * B[z][n][k]   (fp16 A-split 2-term)
// M=768, N=4096, K=768. CTA tile 128x128, BK=32, 3-stage cp.async pipeline.
// 256 threads = 8 warps (2 x 4); each warp computes 64x32.
// smem per array: 128 rows x 80B (32 fp16 data + pad), conflict-free ldmatrix.
// ---------------------------------------------------------------------------
#define TILE 128
#define BK 32
#define T_TILES 24                 // 768 / 32
#define ROWB 80                    // padded row bytes (32*2 data + 16 pad)
#define ABYTES (TILE * ROWB)       // 10240 per array
#define NARR 3                     // Ah, Al, Bh
#define STAGE_BYTES (NARR * ABYTES)
#define STAGES 3
#define SMEM_GEMM (STAGES * STAGE_BYTES)   // 92160

template <int PASS>  // 0: w = Wqkv@x -> g_wbuf ; 1: out = Wout@V -> outp
__global__ void __launch_bounds__(256, 1)
gemm_mma_kernel(float* __restrict__ outp)
{
    extern __shared__ char smem[];
    const uint32_t su = smem_to_u32(smem);
    const int tid = threadIdx.x;
    const int wid = tid >> 5, lid = tid & 31;
    const int nBlk = blockIdx.x, mBlk = blockIdx.y, z = blockIdx.z;

    const __half* bases[NARR];
    bases[0] = g_Ah + (size_t)PASS * CDIM * CDIM + (size_t)mBlk * TILE * CDIM;
    bases[1] = g_Al + (size_t)PASS * CDIM * CDIM + (size_t)mBlk * TILE * CDIM;
    bases[2] = g_Bh + ((size_t)z * NTOK + (size_t)nBlk * TILE) * CDIM;

    auto prefetch = [&](int t, int s) {
        const uint32_t sb = su + s * STAGE_BYTES;
        const int koff = t * BK;
        #pragma unroll
        for (int q = 0; q < 6; q++) {
            const int i   = q * 256 + tid;     // 0..1535
            const int arr = i >> 9;
            const int idx = i & 511;
            const int row = idx >> 2, col = idx & 3;
            const __half* src = bases[arr] + (size_t)row * CDIM + koff + col * 8;
            const uint32_t dst = sb + arr * ABYTES + row * ROWB + col * 16;
            CP_ASYNC16(dst, src);
        }
        CP_COMMIT();
    };

    prefetch(0, 0); prefetch(1, 1); prefetch(2, 2);

    // warp tiling: 2 (m) x 4 (n)
    const int mbase = (wid >> 2) * 64;
    const int nbase = (wid & 3) * 32;
    const int li = lid >> 3, lj = lid & 7;
    const uint32_t aoff = (uint32_t)(mbase + (li & 1) * 8 + lj) * ROWB + (li >> 1) * 16;
    const uint32_t boff = (uint32_t)(nbase + (li >> 1) * 8 + lj) * ROWB + (li & 1) * 16;

    float acc[4][4][4];
    #pragma unroll
    for (int mi = 0; mi < 4; mi++)
        #pragma unroll
        for (int ni = 0; ni < 4; ni++)
            #pragma unroll
            for (int r = 0; r < 4; r++) acc[mi][ni][r] = 0.f;

    for (int t = 0; t < T_TILES; t++) {
        const int s = t % STAGES;
        cp_wait_group<STAGES - 1>();
        __syncthreads();

        const uint32_t sAh = su + s * STAGE_BYTES;
        const uint32_t sAl = sAh + ABYTES;
        const uint32_t sBh = sAh + 2 * ABYTES;

        #pragma unroll
        for (int ks = 0; ks < 2; ks++) {
            const uint32_t ko = ks * 32;   // k-offset bytes (16 fp16)
            uint32_t ah[4][4], al[4][4], bh[4][2];
            #pragma unroll
            for (int mi = 0; mi < 4; mi++) {
                LDSM4(ah[mi][0], ah[mi][1], ah[mi][2], ah[mi][3],
                      sAh + aoff + mi * (16 * ROWB) + ko);
                LDSM4(al[mi][0], al[mi][1], al[mi][2], al[mi][3],
                      sAl + aoff + mi * (16 * ROWB) + ko);
            }
            #pragma unroll
            for (int bi = 0; bi < 2; bi++) {
                uint32_t r0, r1, r2, r3;
                LDSM4(r0, r1, r2, r3, sBh + boff + bi * (16 * ROWB) + ko);
                bh[bi * 2][0] = r0; bh[bi * 2][1] = r1;
                bh[bi * 2 + 1][0] = r2; bh[bi * 2 + 1][1] = r3;
            }
            #pragma unroll
            for (int mi = 0; mi < 4; mi++)
                #pragma unroll
                for (int ni = 0; ni < 4; ni++) {
                    mma16816h(acc[mi][ni], ah[mi], bh[ni]);
                    mma16816h(acc[mi][ni], al[mi], bh[ni]);
                }
        }
        __syncthreads();
        if (t + STAGES < T_TILES) prefetch(t + STAGES, s);
        else CP_COMMIT();   // empty group keeps wait_group accounting aligned
    }

    // epilogue: write fp32 C
    float* Cb = (PASS ? outp : g_wbuf) + (size_t)z * CDIM * NTOK;
    const int gr0 = mBlk * TILE + mbase + (lid >> 2);
    const int gc0 = nBlk * TILE + nbase + (lid & 3) * 2;
    #pragma unroll
    for (int mi = 0; mi < 4; mi++)
        #pragma unroll
        for (int ni = 0; ni < 4; ni++) {
            float* p = Cb + (size_t)(gr0 + mi * 16) * NTOK + gc0 + ni * 8;
            *(float2*)p = make_float2(acc[mi][ni][0], acc[mi][ni][1]);
            *(float2*)(p + (size_t)8 * NTOK) = make_float2(acc[mi][ni][2], acc[mi][ni][3]);
        }
}

// ---------------------------------------------------------------------------
// Split W_qkv / W_out into fp16 hi+lo (K-major layout preserved)
// ---------------------------------------------------------------------------
__global__ void splitW_kernel(const float* __restrict__ Wq, const float* __restrict__ Wo) {
    int i = blockIdx.x * 256 + threadIdx.x;
    if (i >= 2 * CDIM * CDIM) return;
    float v = (i < CDIM * CDIM) ? Wq[i] : Wo[i - CDIM * CDIM];
    __half h = __float2half(v);
    __half l = __float2half(v - __half2float(h));
    g_Ah[i] = h; g_Al[i] = l;
}

// ---------------------------------------------------------------------------
// Transpose [b][c][n] fp32 -> [b][n][c] fp16.  SCALED applies
// v = -w * Pi[b,h(c),n] * attn[b,c] (GEMM2 operand); else v = x.
// ---------------------------------------------------------------------------
template <bool SCALED>
__global__ void split_transpose_kernel(const float* __restrict__ in) {
    __shared__ float tile[32][33];
    const int b = blockIdx.z;
    const int n0 = blockIdx.x * 32, c0 = blockIdx.y * 32;
    const int tx = threadIdx.x, ty = threadIdx.y;
    const float* src = (SCALED ? g_wbuf : in) + (size_t)b * CDIM * NTOK;
    #pragma unroll
    for (int r = 0; r < 4; r++) {
        int c = c0 + ty + r * 8;
        float v = src[(size_t)c * NTOK + n0 + tx];
        if (SCALED) {
            int h = c >> 6;
            v = -v * g_Pi[((size_t)b * HEADS + h) * NTOK + n0 + tx] * g_attn[b * CDIM + c];
        }
        tile[ty + r * 8][tx] = v;
    }
    __syncthreads();
    const size_t obase = ((size_t)b * NTOK + n0) * CDIM + c0;
    #pragma unroll
    for (int r = 0; r < 4; r++) {
        int nn = ty + r * 8;
        g_Bh[obase + (size_t)nn * CDIM + tx] = __float2half(tile[tx][nn]);
    }
}

// ---------------------------------------------------------------------------
// Stats kernels (unchanged from passing R4/R9 version)
// ---------------------------------------------------------------------------
__device__ __forceinline__ float blockReduceSum(float v) {
    __shared__ float sh[32];
    int lane = threadIdx.x & 31, wid = threadIdx.x >> 5;
    #pragma unroll
    for (int o = 16; o; o >>= 1) v += __shfl_down_sync(0xffffffffu, v, o);
    if (lane == 0) sh[wid] = v;
    __syncthreads();
    int nw = blockDim.x >> 5;
    v = (threadIdx.x < nw) ? sh[threadIdx.x] : 0.f;
    if (wid == 0) {
        #pragma unroll
        for (int o = 16; o; o >>= 1) v += __shfl_down_sync(0xffffffffu, v, o);
    }
    return v;
}

__global__ void rownorm_kernel() {
    size_t row = blockIdx.x;
    const float4* p = (const float4*)(g_wbuf + row * NTOK);
    float s = 0.f;
    for (int i = threadIdx.x; i < NTOK / 4; i += 256) {
        float4 v = p[i];
        s += v.x * v.x + v.y * v.y + v.z * v.z + v.w * v.w;
    }
    s = blockReduceSum(s);
    if (threadIdx.x == 0) {
        float nrm = fmaxf(sqrtf(s), 1e-12f);
        g_inv2[row] = 1.f / (nrm * nrm);
    }
}

__global__ void softheads_kernel(const float* __restrict__ temp) {
    const int b = blockIdx.y;
    const int n = blockIdx.x * 128 + threadIdx.x;
    __shared__ float s_inv2[CDIM];
    for (int i = threadIdx.x; i < CDIM; i += 128) s_inv2[i] = g_inv2[b * CDIM + i];
    __syncthreads();
    const float* base = g_wbuf + (size_t)b * CDIM * NTOK + n;
    float logit[HEADS];
    #pragma unroll
    for (int h = 0; h < HEADS; h++) {
        float a = 0.f;
        #pragma unroll 8
        for (int d = 0; d < DHEAD; d++) {
            float v = base[(size_t)(h * DHEAD + d) * NTOK];
            a = fmaf(v * v, s_inv2[h * DHEAD + d], a);
        }
        logit[h] = a * temp[h];
    }
    float m = logit[0];
    #pragma unroll
    for (int h = 1; h < HEADS; h++) m = fmaxf(m, logit[h]);
    float s = 0.f, e[HEADS];
    #pragma unroll
    for (int h = 0; h < HEADS; h++) { e[h] = expf(logit[h] - m); s += e[h]; }
    float inv = 1.f / s;
    float* pp = g_Pi + (size_t)b * HEADS * NTOK + n;
    #pragma unroll
    for (int h = 0; h < HEADS; h++) pp[(size_t)h * NTOK] = e[h] * inv;
}

__global__ void pisum_kernel() {
    int row = blockIdx.x;
    const float* p = g_Pi + (size_t)row * NTOK;
    float s = 0.f;
    for (int i = threadIdx.x; i < NTOK; i += 256) s += p[i];
    s = blockReduceSum(s);
    if (threadIdx.x == 0) g_PiSum[row] = s;
}

__global__ void dots_kernel() {
    int row = blockIdx.x;
    int b = row / CDIM;
    int co = row - b * CDIM;
    int h = co >> 6;
    const float* wp = g_wbuf + (size_t)row * NTOK;
    const float* pp = g_Pi + (size_t)(b * HEADS + h) * NTOK;
    float s = 0.f;
    for (int i = threadIdx.x; i < NTOK; i += 256) {
        float v = wp[i];
        s = fmaf(v * v, pp[i], s);
    }
    s = blockReduceSum(s);
    if (threadIdx.x == 0) {
        float dots = s / (g_PiSum[b * HEADS + h] + 1e-8f);
        g_attn[row] = 1.f / (1.f + dots);
    }
}

// ---------------------------------------------------------------------------
// launch
// ---------------------------------------------------------------------------
extern "C" void kernel_launch(void* const* d_in, const int* in_sizes, int n_in,
                              void* d_out, int out_size) {
    (void)in_sizes; (void)n_in; (void)out_size;
    const float* x     = (const float*)d_in[0];
    const float* W_qkv = (const float*)d_in[1];
    const float* W_out = (const float*)d_in[2];
    const float* temp  = (const float*)d_in[3];
    float* out = (float*)d_out;

    cudaFuncSetAttribute(gemm_mma_kernel<0>, cudaFuncAttributeMaxDynamicSharedMemorySize, SMEM_GEMM);
    cudaFuncSetAttribute(gemm_mma_kernel<1>, cudaFuncAttributeMaxDynamicSharedMemorySize, SMEM_GEMM);

    dim3 gemmGrid(NTOK / TILE, CDIM / TILE, BATCH);     // (32, 6, 16)
    dim3 trGrid(NTOK / 32, CDIM / 32, BATCH);
    dim3 trBlk(32, 8);

    splitW_kernel<<<(2 * CDIM * CDIM + 255) / 256, 256>>>(W_qkv, W_out);
    split_transpose_kernel<false><<<trGrid, trBlk>>>(x);
    gemm_mma_kernel<0><<<gemmGrid, 256, SMEM_GEMM>>>(nullptr);
    rownorm_kernel<<<BATCH * CDIM, 256>>>();
    softheads_kernel<<<dim3(NTOK / 128, BATCH), 128>>>(temp);
    pisum_kernel<<<BATCH * HEADS, 256>>>();
    dots_kernel<<<BATCH * CDIM, 256>>>();
    split_transpose_kernel<true><<<trGrid, trBlk>>>(nullptr);
    gemm_mma_kernel<1><<<gemmGrid, 256, SMEM_GEMM>>>(out);
}

// round 11
// speedup vs baseline: 3.9011x; 1.6316x over previous
#include <cuda_runtime.h>
#include <cuda_fp16.h>
#include <cstdint>

// Problem constants
#define BATCH 16
#define CDIM  768
#define NTOK  4096
#define HEADS 12
#define DHEAD 64

// ---------------------------------------------------------------------------
// Scratch (__device__ globals; no cudaMalloc allowed)
// ---------------------------------------------------------------------------
__device__ float g_wbuf[(size_t)BATCH * CDIM * NTOK];       // w[b][co][n] fp32
__device__ float g_Pi[(size_t)BATCH * HEADS * NTOK];
__device__ float g_inv2[BATCH * CDIM];
__device__ float g_attn[BATCH * CDIM];
__device__ float g_PiSum[BATCH * HEADS];
__device__ __half g_A16[2 * CDIM * CDIM];                   // [W_qkv ; W_out] fp16, [m][k]
__device__ __half g_B16[(size_t)BATCH * NTOK * CDIM];       // B operand fp16, [b][n][k]

// ---------------------------------------------------------------------------
// PTX helpers (baseline sm_80+ features only: cp.async, ldmatrix, mma.sync)
// ---------------------------------------------------------------------------
__device__ __forceinline__ uint32_t smem_to_u32(const void* p) {
    uint32_t a;
    asm("{ .reg .u64 t; cvta.to.shared.u64 t, %1; cvt.u32.u64 %0, t; }" : "=r"(a) : "l"(p));
    return a;
}
#define CP_ASYNC16(dst, src) asm volatile( \
    "cp.async.cg.shared.global [%0], [%1], 16;" :: "r"(dst), "l"(src) : "memory")
#define CP_COMMIT() asm volatile("cp.async.commit_group;" ::: "memory")
template <int N>
__device__ __forceinline__ void cp_wait_group() {
    asm volatile("cp.async.wait_group %0;" :: "n"(N) : "memory");
}
#define LDSM4(r0, r1, r2, r3, addr) asm volatile( \
    "ldmatrix.sync.aligned.m8n8.x4.shared.b16 {%0,%1,%2,%3}, [%4];" \
    : "=r"(r0), "=r"(r1), "=r"(r2), "=r"(r3) : "r"(addr))

__device__ __forceinline__ void mma16816h(float* c, const uint32_t* a, const uint32_t* b) {
    asm volatile(
        "mma.sync.aligned.m16n8k16.row.col.f32.f16.f16.f32 "
        "{%0,%1,%2,%3}, {%4,%5,%6,%7}, {%8,%9}, {%0,%1,%2,%3};"
        : "+f"(c[0]), "+f"(c[1]), "+f"(c[2]), "+f"(c[3])
        : "r"(a[0]), "r"(a[1]), "r"(a[2]), "r"(a[3]), "r"(b[0]), "r"(b[1]));
}

// ---------------------------------------------------------------------------
// GEMM: C[z][m][n] = sum_k A[m][k] * B[z][n][k]   (fp16 single-term)
// M=768, N=4096, K=768. CTA tile 128x128, BK=32, 3-stage cp.async pipeline.
// 256 threads = 8 warps (2 x 4); each warp computes 64x32. 2 CTAs/SM.
// smem per array: 128 rows x 80B (32 fp16 data + pad), conflict-free ldmatrix.
// ---------------------------------------------------------------------------
#define TILE 128
#define BK 32
#define T_TILES 24                 // 768 / 32
#define ROWB 80                    // padded row bytes (32*2 data + 16 pad)
#define ABYTES (TILE * ROWB)       // 10240 per array
#define NARR 2                     // A, B
#define STAGE_BYTES (NARR * ABYTES)
#define STAGES 3
#define SMEM_GEMM (STAGES * STAGE_BYTES)   // 61440 -> 2 CTAs/SM

template <int PASS>  // 0: w = Wqkv@x -> g_wbuf ; 1: out = Wout@V -> outp
__global__ void __launch_bounds__(256, 2)
gemm_mma_kernel(float* __restrict__ outp)
{
    extern __shared__ char smem[];
    const uint32_t su = smem_to_u32(smem);
    const int tid = threadIdx.x;
    const int wid = tid >> 5, lid = tid & 31;
    const int nBlk = blockIdx.x, mBlk = blockIdx.y, z = blockIdx.z;

    const __half* baseA = g_A16 + (size_t)PASS * CDIM * CDIM + (size_t)mBlk * TILE * CDIM;
    const __half* baseB = g_B16 + ((size_t)z * NTOK + (size_t)nBlk * TILE) * CDIM;

    auto prefetch = [&](int t, int s) {
        const uint32_t sb = su + s * STAGE_BYTES;
        const int koff = t * BK;
        #pragma unroll
        for (int q = 0; q < 4; q++) {
            const int i   = q * 256 + tid;     // 0..1023
            const int arr = i >> 9;            // 0: A, 1: B
            const int idx = i & 511;
            const int row = idx >> 2, col = idx & 3;
            const __half* src = (arr ? baseB : baseA) + (size_t)row * CDIM + koff + col * 8;
            const uint32_t dst = sb + arr * ABYTES + row * ROWB + col * 16;
            CP_ASYNC16(dst, src);
        }
        CP_COMMIT();
    };

    prefetch(0, 0); prefetch(1, 1); prefetch(2, 2);

    // warp tiling: 2 (m) x 4 (n)
    const int mbase = (wid >> 2) * 64;
    const int nbase = (wid & 3) * 32;
    const int li = lid >> 3, lj = lid & 7;
    const uint32_t aoff = (uint32_t)(mbase + (li & 1) * 8 + lj) * ROWB + (li >> 1) * 16;
    const uint32_t boff = (uint32_t)(nbase + (li >> 1) * 8 + lj) * ROWB + (li & 1) * 16;

    float acc[4][4][4];
    #pragma unroll
    for (int mi = 0; mi < 4; mi++)
        #pragma unroll
        for (int ni = 0; ni < 4; ni++)
            #pragma unroll
            for (int r = 0; r < 4; r++) acc[mi][ni][r] = 0.f;

    for (int t = 0; t < T_TILES; t++) {
        const int s = t % STAGES;
        cp_wait_group<STAGES - 1>();
        __syncthreads();

        const uint32_t sA = su + s * STAGE_BYTES;
        const uint32_t sB = sA + ABYTES;

        #pragma unroll
        for (int ks = 0; ks < 2; ks++) {
            const uint32_t ko = ks * 32;   // k-offset bytes (16 fp16)
            uint32_t ar[4][4], br[4][2];
            #pragma unroll
            for (int mi = 0; mi < 4; mi++)
                LDSM4(ar[mi][0], ar[mi][1], ar[mi][2], ar[mi][3],
                      sA + aoff + mi * (16 * ROWB) + ko);
            #pragma unroll
            for (int bi = 0; bi < 2; bi++) {
                uint32_t r0, r1, r2, r3;
                LDSM4(r0, r1, r2, r3, sB + boff + bi * (16 * ROWB) + ko);
                br[bi * 2][0] = r0; br[bi * 2][1] = r1;
                br[bi * 2 + 1][0] = r2; br[bi * 2 + 1][1] = r3;
            }
            #pragma unroll
            for (int mi = 0; mi < 4; mi++)
                #pragma unroll
                for (int ni = 0; ni < 4; ni++)
                    mma16816h(acc[mi][ni], ar[mi], br[ni]);
        }
        __syncthreads();
        if (t + STAGES < T_TILES) prefetch(t + STAGES, s);
        else CP_COMMIT();   // empty group keeps wait_group accounting aligned
    }

    // epilogue: write fp32 C
    float* Cb = (PASS ? outp : g_wbuf) + (size_t)z * CDIM * NTOK;
    const int gr0 = mBlk * TILE + mbase + (lid >> 2);
    const int gc0 = nBlk * TILE + nbase + (lid & 3) * 2;
    #pragma unroll
    for (int mi = 0; mi < 4; mi++)
        #pragma unroll
        for (int ni = 0; ni < 4; ni++) {
            float* p = Cb + (size_t)(gr0 + mi * 16) * NTOK + gc0 + ni * 8;
            *(float2*)p = make_float2(acc[mi][ni][0], acc[mi][ni][1]);
            *(float2*)(p + (size_t)8 * NTOK) = make_float2(acc[mi][ni][2], acc[mi][ni][3]);
        }
}

// ---------------------------------------------------------------------------
// Convert W_qkv / W_out to fp16 (K-major layout preserved)
// ---------------------------------------------------------------------------
__global__ void convW_kernel(const float* __restrict__ Wq, const float* __restrict__ Wo) {
    int i = blockIdx.x * 256 + threadIdx.x;
    if (i >= 2 * CDIM * CDIM) return;
    float v = (i < CDIM * CDIM) ? Wq[i] : Wo[i - CDIM * CDIM];
    g_A16[i] = __float2half(v);
}

// ---------------------------------------------------------------------------
// Transpose [b][c][n] fp32 -> [b][n][c] fp16.  SCALED applies
// v = -w * Pi[b,h(c),n] * attn[b,c] (GEMM2 operand); else v = x.
// ---------------------------------------------------------------------------
template <bool SCALED>
__global__ void split_transpose_kernel(const float* __restrict__ in) {
    __shared__ float tile[32][33];
    const int b = blockIdx.z;
    const int n0 = blockIdx.x * 32, c0 = blockIdx.y * 32;
    const int tx = threadIdx.x, ty = threadIdx.y;
    const float* src = (SCALED ? g_wbuf : in) + (size_t)b * CDIM * NTOK;
    #pragma unroll
    for (int r = 0; r < 4; r++) {
        int c = c0 + ty + r * 8;
        float v = src[(size_t)c * NTOK + n0 + tx];
        if (SCALED) {
            int h = c >> 6;
            v = -v * g_Pi[((size_t)b * HEADS + h) * NTOK + n0 + tx] * g_attn[b * CDIM + c];
        }
        tile[ty + r * 8][tx] = v;
    }
    __syncthreads();
    const size_t obase = ((size_t)b * NTOK + n0) * CDIM + c0;
    #pragma unroll
    for (int r = 0; r < 4; r++) {
        int nn = ty + r * 8;
        g_B16[obase + (size_t)nn * CDIM + tx] = __float2half(tile[tx][nn]);
    }
}

// ---------------------------------------------------------------------------
// Stats kernels (unchanged from passing R4/R9/R10 versions)
// ---------------------------------------------------------------------------
__device__ __forceinline__ float blockReduceSum(float v) {
    __shared__ float sh[32];
    int lane = threadIdx.x & 31, wid = threadIdx.x >> 5;
    #pragma unroll
    for (int o = 16; o; o >>= 1) v += __shfl_down_sync(0xffffffffu, v, o);
    if (lane == 0) sh[wid] = v;
    __syncthreads();
    int nw = blockDim.x >> 5;
    v = (threadIdx.x < nw) ? sh[threadIdx.x] : 0.f;
    if (wid == 0) {
        #pragma unroll
        for (int o = 16; o; o >>= 1) v += __shfl_down_sync(0xffffffffu, v, o);
    }
    return v;
}

__global__ void rownorm_kernel() {
    size_t row = blockIdx.x;
    const float4* p = (const float4*)(g_wbuf + row * NTOK);
    float s = 0.f;
    for (int i = threadIdx.x; i < NTOK / 4; i += 256) {
        float4 v = p[i];
        s += v.x * v.x + v.y * v.y + v.z * v.z + v.w * v.w;
    }
    s = blockReduceSum(s);
    if (threadIdx.x == 0) {
        float nrm = fmaxf(sqrtf(s), 1e-12f);
        g_inv2[row] = 1.f / (nrm * nrm);
    }
}

__global__ void softheads_kernel(const float* __restrict__ temp) {
    const int b = blockIdx.y;
    const int n = blockIdx.x * 128 + threadIdx.x;
    __shared__ float s_inv2[CDIM];
    for (int i = threadIdx.x; i < CDIM; i += 128) s_inv2[i] = g_inv2[b * CDIM + i];
    __syncthreads();
    const float* base = g_wbuf + (size_t)b * CDIM * NTOK + n;
    float logit[HEADS];
    #pragma unroll
    for (int h = 0; h < HEADS; h++) {
        float a = 0.f;
        #pragma unroll 8
        for (int d = 0; d < DHEAD; d++) {
            float v = base[(size_t)(h * DHEAD + d) * NTOK];
            a = fmaf(v * v, s_inv2[h * DHEAD + d], a);
        }
        logit[h] = a * temp[h];
    }
    float m = logit[0];
    #pragma unroll
    for (int h = 1; h < HEADS; h++) m = fmaxf(m, logit[h]);
    float s = 0.f, e[HEADS];
    #pragma unroll
    for (int h = 0; h < HEADS; h++) { e[h] = expf(logit[h] - m); s += e[h]; }
    float inv = 1.f / s;
    float* pp = g_Pi + (size_t)b * HEADS * NTOK + n;
    #pragma unroll
    for (int h = 0; h < HEADS; h++) pp[(size_t)h * NTOK] = e[h] * inv;
}

__global__ void pisum_kernel() {
    int row = blockIdx.x;
    const float* p = g_Pi + (size_t)row * NTOK;
    float s = 0.f;
    for (int i = threadIdx.x; i < NTOK; i += 256) s += p[i];
    s = blockReduceSum(s);
    if (threadIdx.x == 0) g_PiSum[row] = s;
}

__global__ void dots_kernel() {
    int row = blockIdx.x;
    int b = row / CDIM;
    int co = row - b * CDIM;
    int h = co >> 6;
    const float* wp = g_wbuf + (size_t)row * NTOK;
    const float* pp = g_Pi + (size_t)(b * HEADS + h) * NTOK;
    float s = 0.f;
    for (int i = threadIdx.x; i < NTOK; i += 256) {
        float v = wp[i];
        s = fmaf(v * v, pp[i], s);
    }
    s = blockReduceSum(s);
    if (threadIdx.x == 0) {
        float dots = s / (g_PiSum[b * HEADS + h] + 1e-8f);
        g_attn[row] = 1.f / (1.f + dots);
    }
}

// ---------------------------------------------------------------------------
// launch
// ---------------------------------------------------------------------------
extern "C" void kernel_launch(void* const* d_in, const int* in_sizes, int n_in,
                              void* d_out, int out_size) {
    (void)in_sizes; (void)n_in; (void)out_size;
    const float* x     = (const float*)d_in[0];
    const float* W_qkv = (const float*)d_in[1];
    const float* W_out = (const float*)d_in[2];
    const float* temp  = (const float*)d_in[3];
    float* out = (float*)d_out;

    cudaFuncSetAttribute(gemm_mma_kernel<0>, cudaFuncAttributeMaxDynamicSharedMemorySize, SMEM_GEMM);
    cudaFuncSetAttribute(gemm_mma_kernel<1>, cudaFuncAttributeMaxDynamicSharedMemorySize, SMEM_GEMM);

    dim3 gemmGrid(NTOK / TILE, CDIM / TILE, BATCH);     // (32, 6, 16)
    dim3 trGrid(NTOK / 32, CDIM / 32, BATCH);
    dim3 trBlk(32, 8);

    convW_kernel<<<(2 * CDIM * CDIM + 255) / 256, 256>>>(W_qkv, W_out);
    split_transpose_kernel<false><<<trGrid, trBlk>>>(x);
    gemm_mma_kernel<0><<<gemmGrid, 256, SMEM_GEMM>>>(nullptr);
    rownorm_kernel<<<BATCH * CDIM, 256>>>();
    softheads_kernel<<<dim3(NTOK / 128, BATCH), 128>>>(temp);
    pisum_kernel<<<BATCH * HEADS, 256>>>();
    dots_kernel<<<BATCH * CDIM, 256>>>();
    split_transpose_kernel<true><<<trGrid, trBlk>>>(nullptr);
    gemm_mma_kernel<1><<<gemmGrid, 256, SMEM_GEMM>>>(out);
}

// round 12
// speedup vs baseline: 4.2258x; 1.0832x over previous
#include <cuda_runtime.h>
#include <cuda_fp16.h>
#include <cstdint>

// Problem constants
#define BATCH 16
#define CDIM  768
#define NTOK  4096
#define HEADS 12
#define DHEAD 64

// ---------------------------------------------------------------------------
// Scratch (__device__ globals; no cudaMalloc allowed)
// ---------------------------------------------------------------------------
__device__ float g_wbuf[(size_t)BATCH * CDIM * NTOK];       // w[b][co][n] fp32
__device__ float g_Pi[(size_t)BATCH * HEADS * NTOK];
__device__ float g_inv2[BATCH * CDIM];
__device__ float g_attn[BATCH * CDIM];
__device__ float g_PiSum[BATCH * HEADS];
__device__ float g_rnPart[(size_t)BATCH * CDIM * 32];       // rownorm partials [row][nBlk]
__device__ float g_dotsP[(size_t)BATCH * 128 * CDIM];       // dots partials [b][blk][co]
__device__ __half g_A16[2 * CDIM * CDIM];                   // [W_qkv ; W_out] fp16, [m][k]
__device__ __half g_B16[(size_t)BATCH * NTOK * CDIM];       // B operand fp16, [b][n][k]

// ---------------------------------------------------------------------------
// PTX helpers (baseline sm_80+ features only: cp.async, ldmatrix, mma.sync)
// ---------------------------------------------------------------------------
__device__ __forceinline__ uint32_t smem_to_u32(const void* p) {
    uint32_t a;
    asm("{ .reg .u64 t; cvta.to.shared.u64 t, %1; cvt.u32.u64 %0, t; }" : "=r"(a) : "l"(p));
    return a;
}
#define CP_ASYNC16(dst, src) asm volatile( \
    "cp.async.cg.shared.global [%0], [%1], 16;" :: "r"(dst), "l"(src) : "memory")
#define CP_COMMIT() asm volatile("cp.async.commit_group;" ::: "memory")
template <int N>
__device__ __forceinline__ void cp_wait_group() {
    asm volatile("cp.async.wait_group %0;" :: "n"(N) : "memory");
}
#define LDSM4(r0, r1, r2, r3, addr) asm volatile( \
    "ldmatrix.sync.aligned.m8n8.x4.shared.b16 {%0,%1,%2,%3}, [%4];" \
    : "=r"(r0), "=r"(r1), "=r"(r2), "=r"(r3) : "r"(addr))

__device__ __forceinline__ void mma16816h(float* c, const uint32_t* a, const uint32_t* b) {
    asm volatile(
        "mma.sync.aligned.m16n8k16.row.col.f32.f16.f16.f32 "
        "{%0,%1,%2,%3}, {%4,%5,%6,%7}, {%8,%9}, {%0,%1,%2,%3};"
        : "+f"(c[0]), "+f"(c[1]), "+f"(c[2]), "+f"(c[3])
        : "r"(a[0]), "r"(a[1]), "r"(a[2]), "r"(a[3]), "r"(b[0]), "r"(b[1]));
}

// ---------------------------------------------------------------------------
// GEMM: C[z][m][n] = sum_k A[m][k] * B[z][n][k]   (fp16 single-term)
// 128x128 CTA tile, BK=32, 4-stage cp.async pipeline, 2 CTAs/SM.
// PASS==0 additionally emits deterministic per-row sum-of-squares partials.
// ---------------------------------------------------------------------------
#define TILE 128
#define BK 32
#define T_TILES 24                 // 768 / 32
#define ROWB 80                    // padded row bytes (32*2 data + 16 pad)
#define ABYTES (TILE * ROWB)       // 10240 per array
#define STAGE_BYTES (2 * ABYTES)   // A, B
#define STAGES 4
#define SMEM_GEMM (STAGES * STAGE_BYTES)   // 81920 -> 2 CTAs/SM (164KB)

template <int PASS>  // 0: w = Wqkv@x -> g_wbuf ; 1: out = Wout@V -> outp
__global__ void __launch_bounds__(256, 2)
gemm_mma_kernel(float* __restrict__ outp)
{
    extern __shared__ char smem[];
    const uint32_t su = smem_to_u32(smem);
    const int tid = threadIdx.x;
    const int wid = tid >> 5, lid = tid & 31;
    const int nBlk = blockIdx.x, mBlk = blockIdx.y, z = blockIdx.z;

    const __half* baseA = g_A16 + (size_t)PASS * CDIM * CDIM + (size_t)mBlk * TILE * CDIM;
    const __half* baseB = g_B16 + ((size_t)z * NTOK + (size_t)nBlk * TILE) * CDIM;

    auto prefetch = [&](int t, int s) {
        const uint32_t sb = su + s * STAGE_BYTES;
        const int koff = t * BK;
        #pragma unroll
        for (int q = 0; q < 4; q++) {
            const int i   = q * 256 + tid;     // 0..1023
            const int arr = i >> 9;            // 0: A, 1: B
            const int idx = i & 511;
            const int row = idx >> 2, col = idx & 3;
            const __half* src = (arr ? baseB : baseA) + (size_t)row * CDIM + koff + col * 8;
            const uint32_t dst = sb + arr * ABYTES + row * ROWB + col * 16;
            CP_ASYNC16(dst, src);
        }
        CP_COMMIT();
    };

    prefetch(0, 0); prefetch(1, 1); prefetch(2, 2); prefetch(3, 3);

    // warp tiling: 2 (m) x 4 (n)
    const int mbase = (wid >> 2) * 64;
    const int nbase = (wid & 3) * 32;
    const int li = lid >> 3, lj = lid & 7;
    const uint32_t aoff = (uint32_t)(mbase + (li & 1) * 8 + lj) * ROWB + (li >> 1) * 16;
    const uint32_t boff = (uint32_t)(nbase + (li >> 1) * 8 + lj) * ROWB + (li & 1) * 16;

    float acc[4][4][4];
    #pragma unroll
    for (int mi = 0; mi < 4; mi++)
        #pragma unroll
        for (int ni = 0; ni < 4; ni++)
            #pragma unroll
            for (int r = 0; r < 4; r++) acc[mi][ni][r] = 0.f;

    for (int t = 0; t < T_TILES; t++) {
        const int s = t % STAGES;
        cp_wait_group<STAGES - 1>();
        __syncthreads();

        const uint32_t sA = su + s * STAGE_BYTES;
        const uint32_t sB = sA + ABYTES;

        #pragma unroll
        for (int ks = 0; ks < 2; ks++) {
            const uint32_t ko = ks * 32;   // k-offset bytes (16 fp16)
            uint32_t ar[4][4], br[4][2];
            #pragma unroll
            for (int mi = 0; mi < 4; mi++)
                LDSM4(ar[mi][0], ar[mi][1], ar[mi][2], ar[mi][3],
                      sA + aoff + mi * (16 * ROWB) + ko);
            #pragma unroll
            for (int bi = 0; bi < 2; bi++) {
                uint32_t r0, r1, r2, r3;
                LDSM4(r0, r1, r2, r3, sB + boff + bi * (16 * ROWB) + ko);
                br[bi * 2][0] = r0; br[bi * 2][1] = r1;
                br[bi * 2 + 1][0] = r2; br[bi * 2 + 1][1] = r3;
            }
            #pragma unroll
            for (int mi = 0; mi < 4; mi++)
                #pragma unroll
                for (int ni = 0; ni < 4; ni++)
                    mma16816h(acc[mi][ni], ar[mi], br[ni]);
        }
        __syncthreads();
        if (t + STAGES < T_TILES) prefetch(t + STAGES, s);
        else CP_COMMIT();   // empty group keeps wait_group accounting aligned
    }

    // epilogue: write fp32 C
    float* Cb = (PASS ? outp : g_wbuf) + (size_t)z * CDIM * NTOK;
    const int gr0 = mBlk * TILE + mbase + (lid >> 2);
    const int gc0 = nBlk * TILE + nbase + (lid & 3) * 2;
    #pragma unroll
    for (int mi = 0; mi < 4; mi++)
        #pragma unroll
        for (int ni = 0; ni < 4; ni++) {
            float* p = Cb + (size_t)(gr0 + mi * 16) * NTOK + gc0 + ni * 8;
            *(float2*)p = make_float2(acc[mi][ni][0], acc[mi][ni][1]);
            *(float2*)(p + (size_t)8 * NTOK) = make_float2(acc[mi][ni][2], acc[mi][ni][3]);
        }

    if constexpr (PASS == 0) {
        // deterministic per-row sumsq partials: quad-shuffle + 4-warp smem reduce
        float* sp = (float*)smem;   // 128 rows x 4 n-warps (smem quiescent now)
        #pragma unroll
        for (int mi = 0; mi < 4; mi++)
            #pragma unroll
            for (int sub = 0; sub < 2; sub++) {
                float v = 0.f;
                #pragma unroll
                for (int ni = 0; ni < 4; ni++) {
                    float a0 = acc[mi][ni][sub * 2 + 0];
                    float a1 = acc[mi][ni][sub * 2 + 1];
                    v += a0 * a0 + a1 * a1;
                }
                v += __shfl_xor_sync(0xffffffffu, v, 1);
                v += __shfl_xor_sync(0xffffffffu, v, 2);
                if ((lid & 3) == 0) {
                    int rl = mbase + mi * 16 + sub * 8 + (lid >> 2);
                    sp[rl * 4 + (wid & 3)] = v;
                }
            }
        __syncthreads();
        if (tid < 128) {
            float v = sp[tid * 4] + sp[tid * 4 + 1] + sp[tid * 4 + 2] + sp[tid * 4 + 3];
            g_rnPart[((size_t)z * CDIM + mBlk * TILE + tid) * 32 + nBlk] = v;
        }
    }
}

// ---------------------------------------------------------------------------
// rownorm partial reduce: inv2 = 1/max(sqrt(sum),1e-12)^2
// ---------------------------------------------------------------------------
__global__ void rownorm_reduce_kernel() {
    int row = blockIdx.x * 256 + threadIdx.x;   // 0 .. BATCH*CDIM-1
    const float4* p = (const float4*)(g_rnPart + (size_t)row * 32);
    float s = 0.f;
    #pragma unroll
    for (int i = 0; i < 8; i++) { float4 v = p[i]; s += v.x + v.y + v.z + v.w; }
    float nrm = fmaxf(sqrtf(s), 1e-12f);
    g_inv2[row] = 1.f / (nrm * nrm);
}

// ---------------------------------------------------------------------------
// Fused stats: per 32-token tile, one read of wbuf ->
//   logits (sum_d w^2*inv2, *temp) -> head-softmax Pi (write g_Pi)
//   -> per-block dots partials sum_t w^2*Pi  (write g_dotsP[b][blk][co])
// smem: w tile as fp16 with stride-34 padding (conflict-free co-strided reads)
// ---------------------------------------------------------------------------
#define FS_STRIDE 34
#define SMEM_FS (CDIM * FS_STRIDE * 2 + CDIM * 4 + 32 * HEADS * 4 + HEADS * 32 * 4)

__global__ void __launch_bounds__(256)
fusedstats_kernel(const float* __restrict__ temp) {
    extern __shared__ char fsmem[];
    __half* s_w    = (__half*)fsmem;                               // [768][34]
    float*  s_inv2 = (float*)(fsmem + CDIM * FS_STRIDE * 2);       // [768]
    float*  s_logit = s_inv2 + CDIM;                               // [32][12]
    float*  s_Pi    = s_logit + 32 * HEADS;                        // [12][32]
    const int b = blockIdx.y, n0 = blockIdx.x * 32, tid = threadIdx.x;
    const float* wb = g_wbuf + (size_t)b * CDIM * NTOK + n0;

    for (int i = tid; i < CDIM * 32; i += 256) {
        int co = i >> 5, t = i & 31;
        s_w[co * FS_STRIDE + t] = __float2half(wb[(size_t)co * NTOK + t]);
    }
    for (int i = tid; i < CDIM; i += 256) s_inv2[i] = g_inv2[b * CDIM + i];
    __syncthreads();

    for (int p = tid; p < 32 * HEADS; p += 256) {
        int t = p & 31, h = p >> 5;
        const __half* wr = s_w + (h * DHEAD) * FS_STRIDE + t;
        const float* iv = s_inv2 + h * DHEAD;
        float a = 0.f;
        #pragma unroll 16
        for (int d = 0; d < DHEAD; d++) {
            float v = __half2float(wr[d * FS_STRIDE]);
            a = fmaf(v * v, iv[d], a);
        }
        s_logit[t * HEADS + h] = a * temp[h];
    }
    __syncthreads();

    if (tid < 32) {
        int t = tid;
        float m = s_logit[t * HEADS];
        #pragma unroll
        for (int h = 1; h < HEADS; h++) m = fmaxf(m, s_logit[t * HEADS + h]);
        float s = 0.f, e[HEADS];
        #pragma unroll
        for (int h = 0; h < HEADS; h++) { e[h] = expf(s_logit[t * HEADS + h] - m); s += e[h]; }
        float inv = 1.f / s;
        #pragma unroll
        for (int h = 0; h < HEADS; h++) {
            float pi = e[h] * inv;
            s_Pi[h * 32 + t] = pi;
            g_Pi[((size_t)b * HEADS + h) * NTOK + n0 + t] = pi;
        }
    }
    __syncthreads();

    for (int co = tid; co < CDIM; co += 256) {
        int h = co >> 6;
        const __half* wr = s_w + co * FS_STRIDE;
        const float* pr = s_Pi + h * 32;
        float s = 0.f;
        #pragma unroll 8
        for (int t = 0; t < 32; t++) {
            float v = __half2float(wr[t]);
            s = fmaf(v * v, pr[t], s);
        }
        g_dotsP[((size_t)b * 128 + blockIdx.x) * CDIM + co] = s;
    }
}

// ---------------------------------------------------------------------------
// pisum + dots reduce
// ---------------------------------------------------------------------------
__device__ __forceinline__ float blockReduceSum(float v) {
    __shared__ float sh[32];
    int lane = threadIdx.x & 31, wid = threadIdx.x >> 5;
    #pragma unroll
    for (int o = 16; o; o >>= 1) v += __shfl_down_sync(0xffffffffu, v, o);
    if (lane == 0) sh[wid] = v;
    __syncthreads();
    int nw = blockDim.x >> 5;
    v = (threadIdx.x < nw) ? sh[threadIdx.x] : 0.f;
    if (wid == 0) {
        #pragma unroll
        for (int o = 16; o; o >>= 1) v += __shfl_down_sync(0xffffffffu, v, o);
    }
    return v;
}

__global__ void pisum_kernel() {
    int row = blockIdx.x;
    const float* p = g_Pi + (size_t)row * NTOK;
    float s = 0.f;
    for (int i = threadIdx.x; i < NTOK; i += 256) s += p[i];
    s = blockReduceSum(s);
    if (threadIdx.x == 0) g_PiSum[row] = s;
}

__global__ void dots_reduce_kernel() {   // grid (CDIM/256, BATCH)
    int b = blockIdx.y, co = blockIdx.x * 256 + threadIdx.x;
    int h = co >> 6;
    const float* p = g_dotsP + (size_t)b * 128 * CDIM + co;
    float s = 0.f;
    for (int blk = 0; blk < 128; blk++) s += p[(size_t)blk * CDIM];
    float dots = s / (g_PiSum[b * HEADS + h] + 1e-8f);
    g_attn[b * CDIM + co] = 1.f / (1.f + dots);
}

// ---------------------------------------------------------------------------
// Convert W_qkv / W_out to fp16 (K-major layout preserved)
// ---------------------------------------------------------------------------
__global__ void convW_kernel(const float* __restrict__ Wq, const float* __restrict__ Wo) {
    int i = blockIdx.x * 256 + threadIdx.x;
    if (i >= 2 * CDIM * CDIM) return;
    float v = (i < CDIM * CDIM) ? Wq[i] : Wo[i - CDIM * CDIM];
    g_A16[i] = __float2half(v);
}

// ---------------------------------------------------------------------------
// Transpose [b][c][n] fp32 -> [b][n][c] fp16.  SCALED applies
// v = -w * Pi[b,h(c),n] * attn[b,c] (GEMM2 operand); else v = x.
// ---------------------------------------------------------------------------
template <bool SCALED>
__global__ void split_transpose_kernel(const float* __restrict__ in) {
    __shared__ float tile[32][33];
    const int b = blockIdx.z;
    const int n0 = blockIdx.x * 32, c0 = blockIdx.y * 32;
    const int tx = threadIdx.x, ty = threadIdx.y;
    const float* src = (SCALED ? g_wbuf : in) + (size_t)b * CDIM * NTOK;
    #pragma unroll
    for (int r = 0; r < 4; r++) {
        int c = c0 + ty + r * 8;
        float v = src[(size_t)c * NTOK + n0 + tx];
        if (SCALED) {
            int h = c >> 6;
            v = -v * g_Pi[((size_t)b * HEADS + h) * NTOK + n0 + tx] * g_attn[b * CDIM + c];
        }
        tile[ty + r * 8][tx] = v;
    }
    __syncthreads();
    const size_t obase = ((size_t)b * NTOK + n0) * CDIM + c0;
    #pragma unroll
    for (int r = 0; r < 4; r++) {
        int nn = ty + r * 8;
        g_B16[obase + (size_t)nn * CDIM + tx] = __float2half(tile[tx][nn]);
    }
}

// ---------------------------------------------------------------------------
// launch
// ---------------------------------------------------------------------------
extern "C" void kernel_launch(void* const* d_in, const int* in_sizes, int n_in,
                              void* d_out, int out_size) {
    (void)in_sizes; (void)n_in; (void)out_size;
    const float* x     = (const float*)d_in[0];
    const float* W_qkv = (const float*)d_in[1];
    const float* W_out = (const float*)d_in[2];
    const float* temp  = (const float*)d_in[3];
    float* out = (float*)d_out;

    cudaFuncSetAttribute(gemm_mma_kernel<0>, cudaFuncAttributeMaxDynamicSharedMemorySize, SMEM_GEMM);
    cudaFuncSetAttribute(gemm_mma_kernel<1>, cudaFuncAttributeMaxDynamicSharedMemorySize, SMEM_GEMM);
    cudaFuncSetAttribute(fusedstats_kernel, cudaFuncAttributeMaxDynamicSharedMemorySize, SMEM_FS);

    dim3 gemmGrid(NTOK / TILE, CDIM / TILE, BATCH);     // (32, 6, 16)
    dim3 trGrid(NTOK / 32, CDIM / 32, BATCH);
    dim3 trBlk(32, 8);

    convW_kernel<<<(2 * CDIM * CDIM + 255) / 256, 256>>>(W_qkv, W_out);
    split_transpose_kernel<false><<<trGrid, trBlk>>>(x);
    gemm_mma_kernel<0><<<gemmGrid, 256, SMEM_GEMM>>>(nullptr);
    rownorm_reduce_kernel<<<BATCH * CDIM / 256, 256>>>();
    fusedstats_kernel<<<dim3(NTOK / 32, BATCH), 256, SMEM_FS>>>(temp);
    pisum_kernel<<<BATCH * HEADS, 256>>>();
    dots_reduce_kernel<<<dim3(CDIM / 256, BATCH), 256>>>();
    split_transpose_kernel<true><<<trGrid, trBlk>>>(nullptr);
    gemm_mma_kernel<1><<<gemmGrid, 256, SMEM_GEMM>>>(out);
}

// round 13
// speedup vs baseline: 4.6768x; 1.1067x over previous
#include <cuda_runtime.h>
#include <cuda_fp16.h>
#include <cstdint>

// Problem constants
#define BATCH 16
#define CDIM  768
#define NTOK  4096
#define HEADS 12
#define DHEAD 64

// ---------------------------------------------------------------------------
// Scratch (__device__ globals; no cudaMalloc allowed)
// ---------------------------------------------------------------------------
__device__ __half g_w16T[(size_t)BATCH * NTOK * CDIM];      // w fp16, [b][n][c]
__device__ float g_Pi[(size_t)BATCH * HEADS * NTOK];
__device__ float g_inv2[BATCH * CDIM];
__device__ float g_attn[BATCH * CDIM];
__device__ float g_PiSum[BATCH * HEADS];
__device__ float g_rnPart[(size_t)BATCH * CDIM * 32];       // rownorm partials [row][nBlk]
__device__ float g_dotsP[(size_t)BATCH * 128 * CDIM];       // dots partials [b][blk][co]
__device__ float g_PiP[(size_t)BATCH * 128 * HEADS];        // Pi-sum partials [b][blk][h]
__device__ __half g_A16[2 * CDIM * CDIM];                   // [W_qkv ; W_out] fp16, [m][k]
__device__ __half g_B16[(size_t)BATCH * NTOK * CDIM];       // B operand fp16, [b][n][k]

// ---------------------------------------------------------------------------
// PTX helpers (baseline sm_80+ features only: cp.async, ldmatrix, mma.sync)
// ---------------------------------------------------------------------------
__device__ __forceinline__ uint32_t smem_to_u32(const void* p) {
    uint32_t a;
    asm("{ .reg .u64 t; cvta.to.shared.u64 t, %1; cvt.u32.u64 %0, t; }" : "=r"(a) : "l"(p));
    return a;
}
#define CP_ASYNC16(dst, src) asm volatile( \
    "cp.async.cg.shared.global [%0], [%1], 16;" :: "r"(dst), "l"(src) : "memory")
#define CP_COMMIT() asm volatile("cp.async.commit_group;" ::: "memory")
template <int N>
__device__ __forceinline__ void cp_wait_group() {
    asm volatile("cp.async.wait_group %0;" :: "n"(N) : "memory");
}
#define LDSM4(r0, r1, r2, r3, addr) asm volatile( \
    "ldmatrix.sync.aligned.m8n8.x4.shared.b16 {%0,%1,%2,%3}, [%4];" \
    : "=r"(r0), "=r"(r1), "=r"(r2), "=r"(r3) : "r"(addr))

__device__ __forceinline__ void mma16816h(float* c, const uint32_t* a, const uint32_t* b) {
    asm volatile(
        "mma.sync.aligned.m16n8k16.row.col.f32.f16.f16.f32 "
        "{%0,%1,%2,%3}, {%4,%5,%6,%7}, {%8,%9}, {%0,%1,%2,%3};"
        : "+f"(c[0]), "+f"(c[1]), "+f"(c[2]), "+f"(c[3])
        : "r"(a[0]), "r"(a[1]), "r"(a[2]), "r"(a[3]), "r"(b[0]), "r"(b[1]));
}

// ---------------------------------------------------------------------------
// GEMM: C[z][m][n] = sum_k A[m][k] * B[z][n][k]   (fp16 single-term)
// 128x128 CTA tile, BK=32, 4-stage cp.async pipeline, 2 CTAs/SM.
// One __syncthreads per k-tile (CUTLASS multistage ordering).
// PASS==0: writes C as fp16 TRANSPOSED [b][n][c] to g_w16T + rownorm partials.
// PASS==1: writes fp32 [b][c][n] to outp.
// ---------------------------------------------------------------------------
#define TILE 128
#define BK 32
#define T_TILES 24                 // 768 / 32
#define ROWB 80                    // padded row bytes (32*2 data + 16 pad)
#define ABYTES (TILE * ROWB)       // 10240 per array
#define STAGE_BYTES (2 * ABYTES)   // A, B
#define STAGES 4
#define SMEM_GEMM (STAGES * STAGE_BYTES)   // 81920 -> 2 CTAs/SM (164KB)
#define TSTRIDE 136                // staging stride (halfs); 272B rows, 16B aligned

template <int PASS>  // 0: w = Wqkv@x -> g_w16T ; 1: out = Wout@V -> outp
__global__ void __launch_bounds__(256, 2)
gemm_mma_kernel(float* __restrict__ outp)
{
    extern __shared__ char smem[];
    const uint32_t su = smem_to_u32(smem);
    const int tid = threadIdx.x;
    const int wid = tid >> 5, lid = tid & 31;
    const int nBlk = blockIdx.x, mBlk = blockIdx.y, z = blockIdx.z;

    const __half* baseA = g_A16 + (size_t)PASS * CDIM * CDIM + (size_t)mBlk * TILE * CDIM;
    const __half* baseB = g_B16 + ((size_t)z * NTOK + (size_t)nBlk * TILE) * CDIM;

    auto prefetch = [&](int t, int s) {
        const uint32_t sb = su + s * STAGE_BYTES;
        const int koff = t * BK;
        #pragma unroll
        for (int q = 0; q < 4; q++) {
            const int i   = q * 256 + tid;     // 0..1023
            const int arr = i >> 9;            // 0: A, 1: B
            const int idx = i & 511;
            const int row = idx >> 2, col = idx & 3;
            const __half* src = (arr ? baseB : baseA) + (size_t)row * CDIM + koff + col * 8;
            const uint32_t dst = sb + arr * ABYTES + row * ROWB + col * 16;
            CP_ASYNC16(dst, src);
        }
        CP_COMMIT();
    };

    prefetch(0, 0); prefetch(1, 1); prefetch(2, 2);   // STAGES-1 in flight

    // warp tiling: 2 (m) x 4 (n)
    const int mbase = (wid >> 2) * 64;
    const int nbase = (wid & 3) * 32;
    const int li = lid >> 3, lj = lid & 7;
    const uint32_t aoff = (uint32_t)(mbase + (li & 1) * 8 + lj) * ROWB + (li >> 1) * 16;
    const uint32_t boff = (uint32_t)(nbase + (li >> 1) * 8 + lj) * ROWB + (li & 1) * 16;

    float acc[4][4][4];
    #pragma unroll
    for (int mi = 0; mi < 4; mi++)
        #pragma unroll
        for (int ni = 0; ni < 4; ni++)
            #pragma unroll
            for (int r = 0; r < 4; r++) acc[mi][ni][r] = 0.f;

    for (int t = 0; t < T_TILES; t++) {
        const int s = t % STAGES;
        cp_wait_group<STAGES - 2>();   // tile t resident
        __syncthreads();               // also releases stage (t-1)%S for overwrite

        if (t + STAGES - 1 < T_TILES) prefetch(t + STAGES - 1, (t + STAGES - 1) % STAGES);
        else CP_COMMIT();              // empty group keeps wait accounting exact

        const uint32_t sA = su + s * STAGE_BYTES;
        const uint32_t sB = sA + ABYTES;

        #pragma unroll
        for (int ks = 0; ks < 2; ks++) {
            const uint32_t ko = ks * 32;   // k-offset bytes (16 fp16)
            uint32_t ar[4][4], br[4][2];
            #pragma unroll
            for (int mi = 0; mi < 4; mi++)
                LDSM4(ar[mi][0], ar[mi][1], ar[mi][2], ar[mi][3],
                      sA + aoff + mi * (16 * ROWB) + ko);
            #pragma unroll
            for (int bi = 0; bi < 2; bi++) {
                uint32_t r0, r1, r2, r3;
                LDSM4(r0, r1, r2, r3, sB + boff + bi * (16 * ROWB) + ko);
                br[bi * 2][0] = r0; br[bi * 2][1] = r1;
                br[bi * 2 + 1][0] = r2; br[bi * 2 + 1][1] = r3;
            }
            #pragma unroll
            for (int mi = 0; mi < 4; mi++)
                #pragma unroll
                for (int ni = 0; ni < 4; ni++)
                    mma16816h(acc[mi][ni], ar[mi], br[ni]);
        }
    }

    if constexpr (PASS == 1) {
        // fp32 write, [b][c][n]
        float* Cb = outp + (size_t)z * CDIM * NTOK;
        const int gr0 = mBlk * TILE + mbase + (lid >> 2);
        const int gc0 = nBlk * TILE + nbase + (lid & 3) * 2;
        #pragma unroll
        for (int mi = 0; mi < 4; mi++)
            #pragma unroll
            for (int ni = 0; ni < 4; ni++) {
                float* p = Cb + (size_t)(gr0 + mi * 16) * NTOK + gc0 + ni * 8;
                *(float2*)p = make_float2(acc[mi][ni][0], acc[mi][ni][1]);
                *(float2*)(p + (size_t)8 * NTOK) = make_float2(acc[mi][ni][2], acc[mi][ni][3]);
            }
    } else {
        // fp16 transposed write via smem staging + rownorm partials
        __syncthreads();   // mainloop smem reads done (tail groups are empty)
        __half* st = (__half*)smem;                          // [128 n][TSTRIDE m]
        float*  sp = (float*)(smem + 128 * TSTRIDE * 2);     // 512 floats

        const int r0 = mbase + (lid >> 2);
        const int c0 = nbase + (lid & 3) * 2;
        #pragma unroll
        for (int mi = 0; mi < 4; mi++)
            #pragma unroll
            for (int ni = 0; ni < 4; ni++) {
                const int r = r0 + mi * 16, c = c0 + ni * 8;
                st[c * TSTRIDE + r]           = __float2half(acc[mi][ni][0]);
                st[(c + 1) * TSTRIDE + r]     = __float2half(acc[mi][ni][1]);
                st[c * TSTRIDE + r + 8]       = __float2half(acc[mi][ni][2]);
                st[(c + 1) * TSTRIDE + r + 8] = __float2half(acc[mi][ni][3]);
            }

        // deterministic per-row sumsq partials: quad-shuffle + 4-warp smem reduce
        #pragma unroll
        for (int mi = 0; mi < 4; mi++)
            #pragma unroll
            for (int sub = 0; sub < 2; sub++) {
                float v = 0.f;
                #pragma unroll
                for (int ni = 0; ni < 4; ni++) {
                    float a0 = acc[mi][ni][sub * 2 + 0];
                    float a1 = acc[mi][ni][sub * 2 + 1];
                    v += a0 * a0 + a1 * a1;
                }
                v += __shfl_xor_sync(0xffffffffu, v, 1);
                v += __shfl_xor_sync(0xffffffffu, v, 2);
                if ((lid & 3) == 0) {
                    int rl = mbase + mi * 16 + sub * 8 + (lid >> 2);
                    sp[rl * 4 + (wid & 3)] = v;
                }
            }
        __syncthreads();

        // coalesced global write: 2 threads per n-row, 64 halfs (128B) each
        {
            const int n = tid >> 1, off = (tid & 1) * 64;
            const uint4* srow = (const uint4*)(st + n * TSTRIDE + off);
            uint4* drow = (uint4*)(g_w16T
                + ((size_t)z * NTOK + nBlk * TILE + n) * CDIM + mBlk * TILE + off);
            #pragma unroll
            for (int i = 0; i < 8; i++) drow[i] = srow[i];
        }
        if (tid < 128) {
            float v = sp[tid * 4] + sp[tid * 4 + 1] + sp[tid * 4 + 2] + sp[tid * 4 + 3];
            g_rnPart[((size_t)z * CDIM + mBlk * TILE + tid) * 32 + nBlk] = v;
        }
    }
}

// ---------------------------------------------------------------------------
// rownorm partial reduce: inv2 = 1/max(sqrt(sum),1e-12)^2
// ---------------------------------------------------------------------------
__global__ void rownorm_reduce_kernel() {
    int row = blockIdx.x * 256 + threadIdx.x;   // 0 .. BATCH*CDIM-1
    const float4* p = (const float4*)(g_rnPart + (size_t)row * 32);
    float s = 0.f;
    #pragma unroll
    for (int i = 0; i < 8; i++) { float4 v = p[i]; s += v.x + v.y + v.z + v.w; }
    float nrm = fmaxf(sqrtf(s), 1e-12f);
    g_inv2[row] = 1.f / (nrm * nrm);
}

// ---------------------------------------------------------------------------
// Fused stats off transposed fp16 w: per 32-token tile, one read ->
//   logits -> head-softmax Pi (g_Pi) -> Pi-sum partials -> dots partials
// smem w tile [t][c] stride 770 halfs (uint32-aligned, conflict-benign)
// ---------------------------------------------------------------------------
#define FS_STRIDE 770
#define SMEM_FS (32 * FS_STRIDE * 2 + CDIM * 4 + 32 * HEADS * 4 + HEADS * 32 * 4)

__global__ void __launch_bounds__(256)
fusedstats_kernel(const float* __restrict__ temp) {
    extern __shared__ char fsmem[];
    __half* s_w     = (__half*)fsmem;                         // [32][770]
    float*  s_inv2  = (float*)(fsmem + 32 * FS_STRIDE * 2);   // [768]
    float*  s_logit = s_inv2 + CDIM;                          // [32][12]
    float*  s_Pi    = s_logit + 32 * HEADS;                   // [12][32]
    const int b = blockIdx.y, blk = blockIdx.x, n0 = blk * 32, tid = threadIdx.x;
    const __half* wb = g_w16T + ((size_t)b * NTOK + n0) * CDIM;

    for (int i = tid; i < 32 * 96; i += 256) {
        int t = i / 96, c8 = (i % 96) * 8;
        uint4 v = *(const uint4*)(wb + (size_t)t * CDIM + c8);
        uint32_t* vv = (uint32_t*)&v;
        uint32_t* dst = (uint32_t*)(s_w + t * FS_STRIDE + c8);
        dst[0] = vv[0]; dst[1] = vv[1]; dst[2] = vv[2]; dst[3] = vv[3];
    }
    for (int i = tid; i < CDIM; i += 256) s_inv2[i] = g_inv2[b * CDIM + i];
    __syncthreads();

    for (int p = tid; p < 32 * HEADS; p += 256) {
        int t = p & 31, h = p >> 5;
        const __half* wr = s_w + t * FS_STRIDE + h * DHEAD;
        const float* iv = s_inv2 + h * DHEAD;
        float a = 0.f;
        #pragma unroll 16
        for (int d = 0; d < DHEAD; d++) {
            float v = __half2float(wr[d]);
            a = fmaf(v * v, iv[d], a);
        }
        s_logit[t * HEADS + h] = a * temp[h];
    }
    __syncthreads();

    if (tid < 32) {
        int t = tid;
        float m = s_logit[t * HEADS];
        #pragma unroll
        for (int h = 1; h < HEADS; h++) m = fmaxf(m, s_logit[t * HEADS + h]);
        float s = 0.f, e[HEADS];
        #pragma unroll
        for (int h = 0; h < HEADS; h++) { e[h] = expf(s_logit[t * HEADS + h] - m); s += e[h]; }
        float inv = 1.f / s;
        #pragma unroll
        for (int h = 0; h < HEADS; h++) {
            float pi = e[h] * inv;
            s_Pi[h * 32 + t] = pi;
            g_Pi[((size_t)b * HEADS + h) * NTOK + n0 + t] = pi;
        }
    }
    __syncthreads();

    if (tid < HEADS) {   // Pi-sum partials (deterministic fixed order)
        float s = 0.f;
        #pragma unroll 8
        for (int t = 0; t < 32; t++) s += s_Pi[tid * 32 + t];
        g_PiP[((size_t)b * 128 + blk) * HEADS + tid] = s;
    }

    for (int co = tid; co < CDIM; co += 256) {
        int h = co >> 6;
        const float* pr = s_Pi + h * 32;
        float s = 0.f;
        #pragma unroll 8
        for (int t = 0; t < 32; t++) {
            float v = __half2float(s_w[t * FS_STRIDE + co]);
            s = fmaf(v * v, pr[t], s);
        }
        g_dotsP[((size_t)b * 128 + blk) * CDIM + co] = s;
    }
}

// ---------------------------------------------------------------------------
// Pi-sum reduce (192 rows x 128 partials) + dots reduce -> attn
// ---------------------------------------------------------------------------
__global__ void pisum_reduce_kernel() {   // 1 block, 192 threads
    int b = threadIdx.x / HEADS, h = threadIdx.x % HEADS;
    float s = 0.f;
    for (int blk = 0; blk < 128; blk++)
        s += g_PiP[((size_t)b * 128 + blk) * HEADS + h];
    g_PiSum[threadIdx.x] = s;
}

__global__ void dots_reduce_kernel() {   // grid (CDIM/256, BATCH)
    int b = blockIdx.y, co = blockIdx.x * 256 + threadIdx.x;
    int h = co >> 6;
    const float* p = g_dotsP + (size_t)b * 128 * CDIM + co;
    float s = 0.f;
    for (int blk = 0; blk < 128; blk++) s += p[(size_t)blk * CDIM];
    float dots = s / (g_PiSum[b * HEADS + h] + 1e-8f);
    g_attn[b * CDIM + co] = 1.f / (1.f + dots);
}

// ---------------------------------------------------------------------------
// Convert W_qkv / W_out to fp16 (K-major layout preserved)
// ---------------------------------------------------------------------------
__global__ void convW_kernel(const float* __restrict__ Wq, const float* __restrict__ Wo) {
    int i = blockIdx.x * 256 + threadIdx.x;
    if (i >= 2 * CDIM * CDIM) return;
    float v = (i < CDIM * CDIM) ? Wq[i] : Wo[i - CDIM * CDIM];
    g_A16[i] = __float2half(v);
}

// ---------------------------------------------------------------------------
// Transpose x: [b][c][n] fp32 -> [b][n][c] fp16 (GEMM1 operand)
// ---------------------------------------------------------------------------
__global__ void xT_kernel(const float* __restrict__ in) {
    __shared__ float tile[32][33];
    const int b = blockIdx.z;
    const int n0 = blockIdx.x * 32, c0 = blockIdx.y * 32;
    const int tx = threadIdx.x, ty = threadIdx.y;
    const float* src = in + (size_t)b * CDIM * NTOK;
    #pragma unroll
    for (int r = 0; r < 4; r++) {
        int c = c0 + ty + r * 8;
        tile[ty + r * 8][tx] = src[(size_t)c * NTOK + n0 + tx];
    }
    __syncthreads();
    const size_t obase = ((size_t)b * NTOK + n0) * CDIM + c0;
    #pragma unroll
    for (int r = 0; r < 4; r++) {
        int nn = ty + r * 8;
        g_B16[obase + (size_t)nn * CDIM + tx] = __float2half(tile[tx][nn]);
    }
}

// ---------------------------------------------------------------------------
// Scale: B16[b][n][c] = -w16T[b][n][c] * Pi[b,h(c),n] * attn[b,c]
// pure streaming, uint4 per thread (8 halfs, one head per chunk)
// ---------------------------------------------------------------------------
__global__ void __launch_bounds__(256)
scale_kernel() {
    size_t base = ((size_t)blockIdx.x * 256 + threadIdx.x) * 8;
    int c = (int)(base % CDIM);
    size_t bn = base / CDIM;
    int n = (int)(bn % NTOK);
    int b = (int)(bn / NTOK);
    int h = c >> 6;
    float sc = -g_Pi[((size_t)b * HEADS + h) * NTOK + n];
    uint4 v = *(const uint4*)(g_w16T + base);
    __half2* hv = (__half2*)&v;
    const float* at = g_attn + b * CDIM + c;
    #pragma unroll
    for (int i = 0; i < 4; i++) {
        float2 f = __half22float2(hv[i]);
        f.x *= sc * at[2 * i];
        f.y *= sc * at[2 * i + 1];
        hv[i] = __floats2half2_rn(f.x, f.y);
    }
    *(uint4*)(g_B16 + base) = v;
}

// ---------------------------------------------------------------------------
// launch
// ---------------------------------------------------------------------------
extern "C" void kernel_launch(void* const* d_in, const int* in_sizes, int n_in,
                              void* d_out, int out_size) {
    (void)in_sizes; (void)n_in; (void)out_size;
    const float* x     = (const float*)d_in[0];
    const float* W_qkv = (const float*)d_in[1];
    const float* W_out = (const float*)d_in[2];
    const float* temp  = (const float*)d_in[3];
    float* out = (float*)d_out;

    cudaFuncSetAttribute(gemm_mma_kernel<0>, cudaFuncAttributeMaxDynamicSharedMemorySize, SMEM_GEMM);
    cudaFuncSetAttribute(gemm_mma_kernel<1>, cudaFuncAttributeMaxDynamicSharedMemorySize, SMEM_GEMM);
    cudaFuncSetAttribute(fusedstats_kernel, cudaFuncAttributeMaxDynamicSharedMemorySize, SMEM_FS);

    dim3 gemmGrid(NTOK / TILE, CDIM / TILE, BATCH);     // (32, 6, 16)
    dim3 trGrid(NTOK / 32, CDIM / 32, BATCH);
    dim3 trBlk(32, 8);

    convW_kernel<<<(2 * CDIM * CDIM + 255) / 256, 256>>>(W_qkv, W_out);
    xT_kernel<<<trGrid, trBlk>>>(x);
    gemm_mma_kernel<0><<<gemmGrid, 256, SMEM_GEMM>>>(nullptr);
    rownorm_reduce_kernel<<<BATCH * CDIM / 256, 256>>>();
    fusedstats_kernel<<<dim3(NTOK / 32, BATCH), 256, SMEM_FS>>>(temp);
    pisum_reduce_kernel<<<1, BATCH * HEADS>>>();
    dots_reduce_kernel<<<dim3(CDIM / 256, BATCH), 256>>>();
    scale_kernel<<<(int)(((size_t)BATCH * NTOK * CDIM / 8) / 256), 256>>>();
    gemm_mma_kernel<1><<<gemmGrid, 256, SMEM_GEMM>>>(out);
}

// round 14
// speedup vs baseline: 5.2323x; 1.1188x over previous
#include <cuda_runtime.h>
#include <cuda_fp16.h>
#include <cstdint>

// Problem constants
#define BATCH 16
#define CDIM  768
#define NTOK  4096
#define HEADS 12
#define DHEAD 64

// ---------------------------------------------------------------------------
// Scratch (__device__ globals; no cudaMalloc allowed)
// ---------------------------------------------------------------------------
__device__ __half g_w16T[(size_t)BATCH * NTOK * CDIM];      // w fp16, [b][n][c]
__device__ float g_Pi[(size_t)BATCH * HEADS * NTOK];
__device__ float g_inv2[BATCH * CDIM];
__device__ float g_attn[BATCH * CDIM];
__device__ float g_PiSum[BATCH * HEADS];
__device__ float g_rnPart[(size_t)BATCH * CDIM * 32];       // rownorm partials [row][nBlk]
__device__ float g_dotsP[(size_t)BATCH * 128 * CDIM];       // dots partials [b][blk][co]
__device__ float g_PiP[(size_t)BATCH * 128 * HEADS];        // Pi-sum partials [b][blk][h]
__device__ __half g_A16[2 * CDIM * CDIM];                   // [W_qkv ; W_out] fp16, [m][k]
__device__ __half g_B16[(size_t)BATCH * NTOK * CDIM];       // B operand fp16, [b][n][k]

// ---------------------------------------------------------------------------
// PTX helpers (baseline sm_80+ features only: cp.async, ldmatrix, mma.sync)
// ---------------------------------------------------------------------------
__device__ __forceinline__ uint32_t smem_to_u32(const void* p) {
    uint32_t a;
    asm("{ .reg .u64 t; cvta.to.shared.u64 t, %1; cvt.u32.u64 %0, t; }" : "=r"(a) : "l"(p));
    return a;
}
#define CP_ASYNC16(dst, src) asm volatile( \
    "cp.async.cg.shared.global [%0], [%1], 16;" :: "r"(dst), "l"(src) : "memory")
#define CP_COMMIT() asm volatile("cp.async.commit_group;" ::: "memory")
template <int N>
__device__ __forceinline__ void cp_wait_group() {
    asm volatile("cp.async.wait_group %0;" :: "n"(N) : "memory");
}
#define LDSM4(r0, r1, r2, r3, addr) asm volatile( \
    "ldmatrix.sync.aligned.m8n8.x4.shared.b16 {%0,%1,%2,%3}, [%4];" \
    : "=r"(r0), "=r"(r1), "=r"(r2), "=r"(r3) : "r"(addr))

__device__ __forceinline__ void mma16816h(float* c, const uint32_t* a, const uint32_t* b) {
    asm volatile(
        "mma.sync.aligned.m16n8k16.row.col.f32.f16.f16.f32 "
        "{%0,%1,%2,%3}, {%4,%5,%6,%7}, {%8,%9}, {%0,%1,%2,%3};"
        : "+f"(c[0]), "+f"(c[1]), "+f"(c[2]), "+f"(c[3])
        : "r"(a[0]), "r"(a[1]), "r"(a[2]), "r"(a[3]), "r"(b[0]), "r"(b[1]));
}

// ---------------------------------------------------------------------------
// GEMM: C[z][m][n] = sum_k A[m][k] * B[z][n][k]   (fp16 single-term)
// 128x128 CTA tile, BK=32, 4-stage cp.async pipeline, 2 CTAs/SM.
// 128 threads = 4 warps (2m x 2n), 64x64 per warp (-33% LDSM traffic vs 64x32).
// PASS==0: writes C as fp16 TRANSPOSED [b][n][c] to g_w16T + rownorm partials.
// PASS==1: writes fp32 [b][c][n] to outp.
// ---------------------------------------------------------------------------
#define TILE 128
#define BK 32
#define T_TILES 24                 // 768 / 32
#define ROWB 80                    // padded row bytes (32*2 data + 16 pad)
#define ABYTES (TILE * ROWB)       // 10240 per array
#define STAGE_BYTES (2 * ABYTES)   // A, B
#define STAGES 4
#define SMEM_GEMM (STAGES * STAGE_BYTES)   // 81920 -> 2 CTAs/SM (164KB)
#define TSTRIDE 136                // staging stride (halfs); 272B rows, 16B aligned

template <int PASS>  // 0: w = Wqkv@x -> g_w16T ; 1: out = Wout@V -> outp
__global__ void __launch_bounds__(128, 2)
gemm_mma_kernel(float* __restrict__ outp)
{
    extern __shared__ char smem[];
    const uint32_t su = smem_to_u32(smem);
    const int tid = threadIdx.x;
    const int wid = tid >> 5, lid = tid & 31;
    const int nBlk = blockIdx.x, mBlk = blockIdx.y, z = blockIdx.z;

    const __half* baseA = g_A16 + (size_t)PASS * CDIM * CDIM + (size_t)mBlk * TILE * CDIM;
    const __half* baseB = g_B16 + ((size_t)z * NTOK + (size_t)nBlk * TILE) * CDIM;

    auto prefetch = [&](int t, int s) {
        const uint32_t sb = su + s * STAGE_BYTES;
        const int koff = t * BK;
        #pragma unroll
        for (int q = 0; q < 8; q++) {
            const int i   = q * 128 + tid;     // 0..1023
            const int arr = i >> 9;            // 0: A, 1: B
            const int idx = i & 511;
            const int row = idx >> 2, col = idx & 3;
            const __half* src = (arr ? baseB : baseA) + (size_t)row * CDIM + koff + col * 8;
            const uint32_t dst = sb + arr * ABYTES + row * ROWB + col * 16;
            CP_ASYNC16(dst, src);
        }
        CP_COMMIT();
    };

    prefetch(0, 0); prefetch(1, 1); prefetch(2, 2);   // STAGES-1 in flight

    // warp tiling: 2 (m) x 2 (n), 64x64 per warp
    const int mbase = (wid >> 1) * 64;
    const int nbase = (wid & 1) * 64;
    const int li = lid >> 3, lj = lid & 7;
    const uint32_t aoff = (uint32_t)(mbase + (li & 1) * 8 + lj) * ROWB + (li >> 1) * 16;
    const uint32_t boff = (uint32_t)(nbase + (li >> 1) * 8 + lj) * ROWB + (li & 1) * 16;

    float acc[4][8][4];
    #pragma unroll
    for (int mi = 0; mi < 4; mi++)
        #pragma unroll
        for (int ni = 0; ni < 8; ni++)
            #pragma unroll
            for (int r = 0; r < 4; r++) acc[mi][ni][r] = 0.f;

    for (int t = 0; t < T_TILES; t++) {
        const int s = t % STAGES;
        cp_wait_group<STAGES - 2>();   // tile t resident
        __syncthreads();               // also releases stage (t-1)%S for overwrite

        if (t + STAGES - 1 < T_TILES) prefetch(t + STAGES - 1, (t + STAGES - 1) % STAGES);
        else CP_COMMIT();              // empty group keeps wait accounting exact

        const uint32_t sA = su + s * STAGE_BYTES;
        const uint32_t sB = sA + ABYTES;

        #pragma unroll
        for (int ks = 0; ks < 2; ks++) {
            const uint32_t ko = ks * 32;   // k-offset bytes (16 fp16)
            uint32_t ar[4][4], br[8][2];
            #pragma unroll
            for (int mi = 0; mi < 4; mi++)
                LDSM4(ar[mi][0], ar[mi][1], ar[mi][2], ar[mi][3],
                      sA + aoff + mi * (16 * ROWB) + ko);
            #pragma unroll
            for (int bi = 0; bi < 4; bi++) {
                uint32_t r0, r1, r2, r3;
                LDSM4(r0, r1, r2, r3, sB + boff + bi * (16 * ROWB) + ko);
                br[bi * 2][0] = r0; br[bi * 2][1] = r1;
                br[bi * 2 + 1][0] = r2; br[bi * 2 + 1][1] = r3;
            }
            #pragma unroll
            for (int mi = 0; mi < 4; mi++)
                #pragma unroll
                for (int ni = 0; ni < 8; ni++)
                    mma16816h(acc[mi][ni], ar[mi], br[ni]);
        }
    }

    if constexpr (PASS == 1) {
        // fp32 write, [b][c][n]
        float* Cb = outp + (size_t)z * CDIM * NTOK;
        const int gr0 = mBlk * TILE + mbase + (lid >> 2);
        const int gc0 = nBlk * TILE + nbase + (lid & 3) * 2;
        #pragma unroll
        for (int mi = 0; mi < 4; mi++)
            #pragma unroll
            for (int ni = 0; ni < 8; ni++) {
                float* p = Cb + (size_t)(gr0 + mi * 16) * NTOK + gc0 + ni * 8;
                *(float2*)p = make_float2(acc[mi][ni][0], acc[mi][ni][1]);
                *(float2*)(p + (size_t)8 * NTOK) = make_float2(acc[mi][ni][2], acc[mi][ni][3]);
            }
    } else {
        // fp16 transposed write via smem staging + rownorm partials
        __syncthreads();   // mainloop smem reads done (tail groups are empty)
        __half* st = (__half*)smem;                          // [128 n][TSTRIDE m]
        float*  sp = (float*)(smem + 128 * TSTRIDE * 2);     // 256 floats

        const int r0 = mbase + (lid >> 2);
        const int c0 = nbase + (lid & 3) * 2;
        #pragma unroll
        for (int mi = 0; mi < 4; mi++)
            #pragma unroll
            for (int ni = 0; ni < 8; ni++) {
                const int r = r0 + mi * 16, c = c0 + ni * 8;
                st[c * TSTRIDE + r]           = __float2half(acc[mi][ni][0]);
                st[(c + 1) * TSTRIDE + r]     = __float2half(acc[mi][ni][1]);
                st[c * TSTRIDE + r + 8]       = __float2half(acc[mi][ni][2]);
                st[(c + 1) * TSTRIDE + r + 8] = __float2half(acc[mi][ni][3]);
            }

        // deterministic per-row sumsq partials: quad-shuffle + 2-warp smem reduce
        #pragma unroll
        for (int mi = 0; mi < 4; mi++)
            #pragma unroll
            for (int sub = 0; sub < 2; sub++) {
                float v = 0.f;
                #pragma unroll
                for (int ni = 0; ni < 8; ni++) {
                    float a0 = acc[mi][ni][sub * 2 + 0];
                    float a1 = acc[mi][ni][sub * 2 + 1];
                    v += a0 * a0 + a1 * a1;
                }
                v += __shfl_xor_sync(0xffffffffu, v, 1);
                v += __shfl_xor_sync(0xffffffffu, v, 2);
                if ((lid & 3) == 0) {
                    int rl = mbase + mi * 16 + sub * 8 + (lid >> 2);
                    sp[rl * 2 + (wid & 1)] = v;
                }
            }
        __syncthreads();

        // coalesced global write: 16 uint4 chunks per n-row, threads sweep rows
        #pragma unroll
        for (int it = 0; it < 16; it++) {
            const int idx = it * 128 + tid;       // 0..2047
            const int n = idx >> 4, cch = idx & 15;
            uint4 v = *(const uint4*)(st + n * TSTRIDE + cch * 8);
            *(uint4*)(g_w16T + ((size_t)z * NTOK + nBlk * TILE + n) * CDIM
                      + mBlk * TILE + cch * 8) = v;
        }
        {
            float v = sp[tid * 2] + sp[tid * 2 + 1];
            g_rnPart[((size_t)z * CDIM + mBlk * TILE + tid) * 32 + nBlk] = v;
        }
    }
}

// ---------------------------------------------------------------------------
// rownorm partial reduce: inv2 = 1/max(sqrt(sum),1e-12)^2
// ---------------------------------------------------------------------------
__global__ void rownorm_reduce_kernel() {
    int row = blockIdx.x * 256 + threadIdx.x;   // 0 .. BATCH*CDIM-1
    const float4* p = (const float4*)(g_rnPart + (size_t)row * 32);
    float s = 0.f;
    #pragma unroll
    for (int i = 0; i < 8; i++) { float4 v = p[i]; s += v.x + v.y + v.z + v.w; }
    float nrm = fmaxf(sqrtf(s), 1e-12f);
    g_inv2[row] = 1.f / (nrm * nrm);
}

// ---------------------------------------------------------------------------
// Fused stats off transposed fp16 w: per 32-token tile, one read ->
//   logits -> head-softmax Pi (g_Pi) -> Pi-sum partials -> dots partials
// ---------------------------------------------------------------------------
#define FS_STRIDE 770
#define SMEM_FS (32 * FS_STRIDE * 2 + CDIM * 4 + 32 * HEADS * 4 + HEADS * 32 * 4)

__global__ void __launch_bounds__(256)
fusedstats_kernel(const float* __restrict__ temp) {
    extern __shared__ char fsmem[];
    __half* s_w     = (__half*)fsmem;                         // [32][770]
    float*  s_inv2  = (float*)(fsmem + 32 * FS_STRIDE * 2);   // [768]
    float*  s_logit = s_inv2 + CDIM;                          // [32][12]
    float*  s_Pi    = s_logit + 32 * HEADS;                   // [12][32]
    const int b = blockIdx.y, blk = blockIdx.x, n0 = blk * 32, tid = threadIdx.x;
    const __half* wb = g_w16T + ((size_t)b * NTOK + n0) * CDIM;

    for (int i = tid; i < 32 * 96; i += 256) {
        int t = i / 96, c8 = (i % 96) * 8;
        uint4 v = *(const uint4*)(wb + (size_t)t * CDIM + c8);
        uint32_t* vv = (uint32_t*)&v;
        uint32_t* dst = (uint32_t*)(s_w + t * FS_STRIDE + c8);
        dst[0] = vv[0]; dst[1] = vv[1]; dst[2] = vv[2]; dst[3] = vv[3];
    }
    for (int i = tid; i < CDIM; i += 256) s_inv2[i] = g_inv2[b * CDIM + i];
    __syncthreads();

    for (int p = tid; p < 32 * HEADS; p += 256) {
        int t = p & 31, h = p >> 5;
        const __half* wr = s_w + t * FS_STRIDE + h * DHEAD;
        const float* iv = s_inv2 + h * DHEAD;
        float a = 0.f;
        #pragma unroll 16
        for (int d = 0; d < DHEAD; d++) {
            float v = __half2float(wr[d]);
            a = fmaf(v * v, iv[d], a);
        }
        s_logit[t * HEADS + h] = a * temp[h];
    }
    __syncthreads();

    if (tid < 32) {
        int t = tid;
        float m = s_logit[t * HEADS];
        #pragma unroll
        for (int h = 1; h < HEADS; h++) m = fmaxf(m, s_logit[t * HEADS + h]);
        float s = 0.f, e[HEADS];
        #pragma unroll
        for (int h = 0; h < HEADS; h++) { e[h] = expf(s_logit[t * HEADS + h] - m); s += e[h]; }
        float inv = 1.f / s;
        #pragma unroll
        for (int h = 0; h < HEADS; h++) {
            float pi = e[h] * inv;
            s_Pi[h * 32 + t] = pi;
            g_Pi[((size_t)b * HEADS + h) * NTOK + n0 + t] = pi;
        }
    }
    __syncthreads();

    if (tid < HEADS) {   // Pi-sum partials (deterministic fixed order)
        float s = 0.f;
        #pragma unroll 8
        for (int t = 0; t < 32; t++) s += s_Pi[tid * 32 + t];
        g_PiP[((size_t)b * 128 + blk) * HEADS + tid] = s;
    }

    for (int co = tid; co < CDIM; co += 256) {
        int h = co >> 6;
        const float* pr = s_Pi + h * 32;
        float s = 0.f;
        #pragma unroll 8
        for (int t = 0; t < 32; t++) {
            float v = __half2float(s_w[t * FS_STRIDE + co]);
            s = fmaf(v * v, pr[t], s);
        }
        g_dotsP[((size_t)b * 128 + blk) * CDIM + co] = s;
    }
}

// ---------------------------------------------------------------------------
// Pi-sum reduce + dots reduce -> attn
// ---------------------------------------------------------------------------
__global__ void pisum_reduce_kernel() {   // 1 block, 192 threads
    int b = threadIdx.x / HEADS, h = threadIdx.x % HEADS;
    float s = 0.f;
    for (int blk = 0; blk < 128; blk++)
        s += g_PiP[((size_t)b * 128 + blk) * HEADS + h];
    g_PiSum[threadIdx.x] = s;
}

__global__ void dots_reduce_kernel() {   // grid (CDIM/256, BATCH)
    int b = blockIdx.y, co = blockIdx.x * 256 + threadIdx.x;
    int h = co >> 6;
    const float* p = g_dotsP + (size_t)b * 128 * CDIM + co;
    float s = 0.f;
    for (int blk = 0; blk < 128; blk++) s += p[(size_t)blk * CDIM];
    float dots = s / (g_PiSum[b * HEADS + h] + 1e-8f);
    g_attn[b * CDIM + co] = 1.f / (1.f + dots);
}

// ---------------------------------------------------------------------------
// Convert W_qkv / W_out to fp16 (K-major layout preserved)
// ---------------------------------------------------------------------------
__global__ void convW_kernel(const float* __restrict__ Wq, const float* __restrict__ Wo) {
    int i = blockIdx.x * 256 + threadIdx.x;
    if (i >= 2 * CDIM * CDIM) return;
    float v = (i < CDIM * CDIM) ? Wq[i] : Wo[i - CDIM * CDIM];
    g_A16[i] = __float2half(v);
}

// ---------------------------------------------------------------------------
// Transpose x: [b][c][n] fp32 -> [b][n][c] fp16 (GEMM1 operand)
// ---------------------------------------------------------------------------
__global__ void xT_kernel(const float* __restrict__ in) {
    __shared__ float tile[32][33];
    const int b = blockIdx.z;
    const int n0 = blockIdx.x * 32, c0 = blockIdx.y * 32;
    const int tx = threadIdx.x, ty = threadIdx.y;
    const float* src = in + (size_t)b * CDIM * NTOK;
    #pragma unroll
    for (int r = 0; r < 4; r++) {
        int c = c0 + ty + r * 8;
        tile[ty + r * 8][tx] = src[(size_t)c * NTOK + n0 + tx];
    }
    __syncthreads();
    const size_t obase = ((size_t)b * NTOK + n0) * CDIM + c0;
    #pragma unroll
    for (int r = 0; r < 4; r++) {
        int nn = ty + r * 8;
        g_B16[obase + (size_t)nn * CDIM + tx] = __float2half(tile[tx][nn]);
    }
}

// ---------------------------------------------------------------------------
// Scale: B16[b][n][c] = -w16T[b][n][c] * Pi[b,h(c),n] * attn[b,c]
// ---------------------------------------------------------------------------
__global__ void __launch_bounds__(256)
scale_kernel() {
    size_t base = ((size_t)blockIdx.x * 256 + threadIdx.x) * 8;
    int c = (int)(base % CDIM);
    size_t bn = base / CDIM;
    int n = (int)(bn % NTOK);
    int b = (int)(bn / NTOK);
    int h = c >> 6;
    float sc = -g_Pi[((size_t)b * HEADS + h) * NTOK + n];
    uint4 v = *(const uint4*)(g_w16T + base);
    __half2* hv = (__half2*)&v;
    const float* at = g_attn + b * CDIM + c;
    #pragma unroll
    for (int i = 0; i < 4; i++) {
        float2 f = __half22float2(hv[i]);
        f.x *= sc * at[2 * i];
        f.y *= sc * at[2 * i + 1];
        hv[i] = __floats2half2_rn(f.x, f.y);
    }
    *(uint4*)(g_B16 + base) = v;
}

// ---------------------------------------------------------------------------
// launch
// ---------------------------------------------------------------------------
extern "C" void kernel_launch(void* const* d_in, const int* in_sizes, int n_in,
                              void* d_out, int out_size) {
    (void)in_sizes; (void)n_in; (void)out_size;
    const float* x     = (const float*)d_in[0];
    const float* W_qkv = (const float*)d_in[1];
    const float* W_out = (const float*)d_in[2];
    const float* temp  = (const float*)d_in[3];
    float* out = (float*)d_out;

    cudaFuncSetAttribute(gemm_mma_kernel<0>, cudaFuncAttributeMaxDynamicSharedMemorySize, SMEM_GEMM);
    cudaFuncSetAttribute(gemm_mma_kernel<1>, cudaFuncAttributeMaxDynamicSharedMemorySize, SMEM_GEMM);
    cudaFuncSetAttribute(fusedstats_kernel, cudaFuncAttributeMaxDynamicSharedMemorySize, SMEM_FS);

    dim3 gemmGrid(NTOK / TILE, CDIM / TILE, BATCH);     // (32, 6, 16)
    dim3 trGrid(NTOK / 32, CDIM / 32, BATCH);
    dim3 trBlk(32, 8);

    convW_kernel<<<(2 * CDIM * CDIM + 255) / 256, 256>>>(W_qkv, W_out);
    xT_kernel<<<trGrid, trBlk>>>(x);
    gemm_mma_kernel<0><<<gemmGrid, 128, SMEM_GEMM>>>(nullptr);
    rownorm_reduce_kernel<<<BATCH * CDIM / 256, 256>>>();
    fusedstats_kernel<<<dim3(NTOK / 32, BATCH), 256, SMEM_FS>>>(temp);
    pisum_reduce_kernel<<<1, BATCH * HEADS>>>();
    dots_reduce_kernel<<<dim3(CDIM / 256, BATCH), 256>>>();
    scale_kernel<<<(int)(((size_t)BATCH * NTOK * CDIM / 8) / 256), 256>>>();
    gemm_mma_kernel<1><<<gemmGrid, 128, SMEM_GEMM>>>(out);
}